// round 6
// baseline (speedup 1.0000x reference)
#include <cuda_runtime.h>
#include <cstdint>
#include <cstdio>

#define D 64
#define NNODES 16384
#define NE 32768
#define NG 256
#define TPQ 12
#define NT (NG * TPQ)   // 3072

// ---------------- scratch (static device allocations) ----------------
__device__ float g_ew[(size_t)NE * (D * D)];   // 512 MB
__device__ float g_hidden[NE * D];
__device__ float g_x[NNODES * D];              // out == h
__device__ float g_agg[NNODES * D];
__device__ float g_deg[NNODES];
__device__ float g_gru_wihT[64 * 192];
__device__ float g_gru_whhT[64 * 192];
__device__ float g_s2s_wihT[128 * 256];
__device__ float g_s2s_whhT[64 * 256];
__device__ float g_mem_wihT[128 * 256];
__device__ float g_lin1T[320 * 64];
__device__ float g_hx[NG * D];

__device__ __forceinline__ float sigf(float x) { return 1.0f / (1.0f + expf(-x)); }
__device__ __forceinline__ uint32_t f2tf32(float f) {
    uint32_t r; asm("cvt.rna.tf32.f32 %0, %1;" : "=r"(r) : "f"(f)); return r;
}

// ---------------- prologue kernels ----------------
// hidden = relu(edge_attr @ e1_w^T + e1_b)
__global__ void k_hidden(const float* __restrict__ ea, const float* __restrict__ w,
                         const float* __restrict__ b, float* __restrict__ out) {
    int i = blockIdx.x * blockDim.x + threadIdx.x;
    if (i >= NE * D) return;
    int e = i >> 6, j = i & 63;
    float v = b[j];
#pragma unroll
    for (int k = 0; k < 6; k++) v += ea[e * 6 + k] * w[j * 6 + k];
    out[i] = fmaxf(v, 0.0f);
}

// x = relu(pos @ lin0_w^T + b); also zero agg and deg
__global__ void k_lin0z(const float* __restrict__ x, const float* __restrict__ w,
                        const float* __restrict__ b, float* __restrict__ out,
                        float* __restrict__ agg, float* __restrict__ deg) {
    int i = blockIdx.x * blockDim.x + threadIdx.x;
    if (i >= NNODES * D) return;
    int n = i >> 6, o = i & 63;
    float v = b[o] + x[n * 3 + 0] * w[o * 3 + 0] + x[n * 3 + 1] * w[o * 3 + 1] +
              x[n * 3 + 2] * w[o * 3 + 2];
    out[i] = fmaxf(v, 0.0f);
    agg[i] = 0.0f;
    if (o == 0) deg[n] = 0.0f;
}

// all weight transposes in one launch
__global__ void k_prep(const float* __restrict__ gru_wih, const float* __restrict__ gru_whh,
                       const float* __restrict__ s2s_wih, const float* __restrict__ s2s_whh,
                       const float* __restrict__ mem_wih, const float* __restrict__ lin1_w,
                       float* __restrict__ gruWihT, float* __restrict__ gruWhhT,
                       float* __restrict__ s2swihT, float* __restrict__ s2swhhT,
                       float* __restrict__ memwihT, float* __restrict__ lin1T) {
    int i = blockIdx.x * blockDim.x + threadIdx.x;
    if (i < 12288) {                      // gru_wih [192,64] -> [64,192]
        int r = i / 64, c = i % 64;
        gruWihT[c * 192 + r] = gru_wih[i];
    } else if (i < 24576) {               // gru_whh
        int j = i - 12288;
        int r = j / 64, c = j % 64;
        gruWhhT[c * 192 + r] = gru_whh[j];
    } else if (i < 57344) {               // s2s_wih [256,128] -> [128,256]
        int j = i - 24576;
        int r = j / 128, c = j % 128;
        s2swihT[c * 256 + r] = s2s_wih[j];
    } else if (i < 73728) {               // s2s_whh [256,64] -> [64,256]
        int j = i - 57344;
        int r = j / 64, c = j % 64;
        s2swhhT[c * 256 + r] = s2s_whh[j];
    } else if (i < 106496) {              // mem_wih [256,128] -> [128,256]
        int j = i - 73728;
        int r = j / 128, c = j % 128;
        memwihT[c * 256 + r] = mem_wih[j];
    } else if (i < 126976) {              // lin1_w [64,320] -> [320,64]
        int j = i - 106496;
        int r = j / 320, c = j % 320;
        lin1T[c * 64 + r] = lin1_w[j];
    }
}

__global__ void k_deg(const int* __restrict__ eidx, float* __restrict__ deg) {
    int e = blockIdx.x * blockDim.x + threadIdx.x;
    if (e < NE) atomicAdd(&deg[eidx[NE + e]], 1.0f);
}

// ---------------- tf32 MMA GEMM: ew[E,4096] = hidden[E,64] @ e2_w[4096,64]^T + b2 ------
__global__ void __launch_bounds__(256) k_ew_tf32(
    const float* __restrict__ A, const float* __restrict__ B,
    const float* __restrict__ bias, float* __restrict__ C) {
    __shared__ uint32_t As[64 * 68];
    __shared__ uint32_t Bs[64 * 68];
    int t = threadIdx.x;
    int m0 = blockIdx.y << 6, n0 = blockIdx.x << 6;
#pragma unroll
    for (int i = t; i < 1024; i += 256) {
        int r = i >> 4, c4 = (i & 15) << 2;
        float4 va = *(const float4*)(A + (size_t)(m0 + r) * 64 + c4);
        uint32_t* da = &As[r * 68 + c4];
        da[0] = f2tf32(va.x); da[1] = f2tf32(va.y); da[2] = f2tf32(va.z); da[3] = f2tf32(va.w);
        float4 vb = *(const float4*)(B + (size_t)(n0 + r) * 64 + c4);
        uint32_t* db = &Bs[r * 68 + c4];
        db[0] = f2tf32(vb.x); db[1] = f2tf32(vb.y); db[2] = f2tf32(vb.z); db[3] = f2tf32(vb.w);
    }
    __syncthreads();
    int lane = t & 31, w = t >> 5;
    int wm = (w >> 1) << 4;   // 0,16,32,48
    int wn = (w & 1) << 5;    // 0,32
    int grp = lane >> 2, tig = lane & 3;
    float acc[4][4];
#pragma unroll
    for (int a = 0; a < 4; a++)
#pragma unroll
        for (int c = 0; c < 4; c++) acc[a][c] = 0.0f;

#pragma unroll
    for (int k0 = 0; k0 < 64; k0 += 8) {
        uint32_t af[4];
        int row = wm + grp;
        af[0] = As[row * 68 + k0 + tig];
        af[1] = As[(row + 8) * 68 + k0 + tig];
        af[2] = As[row * 68 + k0 + tig + 4];
        af[3] = As[(row + 8) * 68 + k0 + tig + 4];
#pragma unroll
        for (int nt = 0; nt < 4; nt++) {
            int col = wn + (nt << 3) + grp;
            uint32_t b0 = Bs[col * 68 + k0 + tig];
            uint32_t b1 = Bs[col * 68 + k0 + tig + 4];
            asm volatile(
                "mma.sync.aligned.m16n8k8.row.col.f32.tf32.tf32.f32 "
                "{%0,%1,%2,%3}, {%4,%5,%6,%7}, {%8,%9}, {%0,%1,%2,%3};\n"
                : "+f"(acc[nt][0]), "+f"(acc[nt][1]), "+f"(acc[nt][2]), "+f"(acc[nt][3])
                : "r"(af[0]), "r"(af[1]), "r"(af[2]), "r"(af[3]), "r"(b0), "r"(b1));
        }
    }
    int row = m0 + wm + grp;
#pragma unroll
    for (int nt = 0; nt < 4; nt++) {
        int col = n0 + wn + (nt << 3) + (tig << 1);
        float b0v = bias[col], b1v = bias[col + 1];
        *(float2*)(C + (size_t)row * 4096 + col) =
            make_float2(acc[nt][0] + b0v, acc[nt][1] + b1v);
        *(float2*)(C + (size_t)(row + 8) * 4096 + col) =
            make_float2(acc[nt][2] + b0v, acc[nt][3] + b1v);
    }
}

// ---------------- per-edge einsum + scatter ----------------
__global__ void k_msg(const float* __restrict__ x, const int* __restrict__ eidx,
                      const float* __restrict__ ew, float* __restrict__ agg) {
    int w = threadIdx.x >> 5, lane = threadIdx.x & 31;
    int e = blockIdx.x * 8 + w;
    int src = eidx[e], dst = eidx[NE + e];
    __shared__ float so[8][64];
    so[w][lane] = x[(size_t)src * 64 + lane];
    so[w][lane + 32] = x[(size_t)src * 64 + 32 + lane];
    __syncwarp();
    const float2* p = (const float2*)(ew + (size_t)e * 4096) + lane;
    float ax = 0.0f, ay = 0.0f;
#pragma unroll 16
    for (int i = 0; i < 64; i++) {
        float s = so[w][i];
        float2 v = p[i * 32];
        ax += s * v.x;
        ay += s * v.y;
    }
    atomicAdd(&agg[(size_t)dst * 64 + 2 * lane], ax);
    atomicAdd(&agg[(size_t)dst * 64 + 2 * lane + 1], ay);
}

// ---------------- fused node update: m = relu(agg/deg + x@root_w + b); GRU; zero agg ----
__global__ void __launch_bounds__(512, 1)
k_node(const float* __restrict__ root_w, const float* __restrict__ conv_b,
       float* __restrict__ agg, const float* __restrict__ deg,
       const float* __restrict__ wihT, const float* __restrict__ whhT,
       const float* __restrict__ bih, const float* __restrict__ bhh,
       float* __restrict__ x) {
    __shared__ float sx[64][64];
    __shared__ float sm[64][64];
    int t = threadIdx.x;
    int n0 = blockIdx.x << 6;
    for (int i = t; i < 1024; i += 512) {
        int r = i >> 4, c = (i & 15) << 2;
        *(float4*)&sx[r][c] = *(const float4*)(x + (size_t)(n0 + r) * 64 + c);
    }
    __syncthreads();
    int o = t & 63, nb = (t >> 6) << 3;
    // phase 1: m = relu(x@root_w + conv_b + agg/deg); reset agg
    float racc[8] = {};
#pragma unroll 4
    for (int k = 0; k < 64; k++) {
        float rw = root_w[k * 64 + o];
#pragma unroll
        for (int j = 0; j < 8; j++) racc[j] += sx[nb + j][k] * rw;
    }
    float cb = conv_b[o];
#pragma unroll
    for (int j = 0; j < 8; j++) {
        int gn = n0 + nb + j;
        float a = agg[(size_t)gn * 64 + o];
        agg[(size_t)gn * 64 + o] = 0.0f;
        sm[nb + j][o] = fmaxf(racc[j] + cb + a * (1.0f / fmaxf(deg[gn], 1.0f)), 0.0f);
    }
    __syncthreads();
    // phase 2: GRU
    float a0[8] = {}, a1[8] = {}, a2[8] = {}, b0[8] = {}, b1[8] = {}, b2[8] = {};
#pragma unroll 4
    for (int k = 0; k < 64; k++) {
        float wi0 = wihT[k * 192 + o];
        float wi1 = wihT[k * 192 + 64 + o];
        float wi2 = wihT[k * 192 + 128 + o];
        float wh0 = whhT[k * 192 + o];
        float wh1 = whhT[k * 192 + 64 + o];
        float wh2 = whhT[k * 192 + 128 + o];
#pragma unroll
        for (int j = 0; j < 8; j++) {
            float mv = sm[nb + j][k];
            float xv = sx[nb + j][k];
            a0[j] += mv * wi0; a1[j] += mv * wi1; a2[j] += mv * wi2;
            b0[j] += xv * wh0; b1[j] += xv * wh1; b2[j] += xv * wh2;
        }
    }
    float bi0 = bih[o], bi1 = bih[64 + o], bi2 = bih[128 + o];
    float bh0 = bhh[o], bh1 = bhh[64 + o], bh2 = bhh[128 + o];
#pragma unroll
    for (int j = 0; j < 8; j++) {
        int n = n0 + nb + j;
        float r = sigf(a0[j] + bi0 + b0[j] + bh0);
        float z = sigf(a1[j] + bi1 + b1[j] + bh1);
        float nn = tanhf(a2[j] + bi2 + r * (b2[j] + bh2));
        float h = sx[nb + j][o];
        x[(size_t)n * 64 + o] = (1.0f - z) * nn + z * h;
    }
}

// ---------------- fused Set2Set (6 steps) + memory LSTM, one block per graph ----------
__global__ void __launch_bounds__(256) k_pool(
    const float* __restrict__ x,
    const float* __restrict__ s2swihT, const float* __restrict__ s2swhhT,
    const float* __restrict__ s2s_bih, const float* __restrict__ s2s_bhh,
    const float* __restrict__ memwihT, const float* __restrict__ mem_bih,
    const float* __restrict__ mem_bhh,
    float* __restrict__ hx, float* __restrict__ out, int out_size) {
    int g = blockIdx.x, t = threadIdx.x;
    __shared__ float so[64][65];
    __shared__ float q[128], hh[64], ch[64], sgate[256], sa[64], red[64];
    for (int idx = t; idx < 4096; idx += 256) {
        int n = idx >> 6, c = idx & 63;
        so[n][c] = x[((size_t)g * 64 + n) * 64 + c];
    }
    if (t < 128) q[t] = 0.0f;
    if (t < 64) { hh[t] = 0.0f; ch[t] = 0.0f; }
    __syncthreads();
    for (int step = 0; step < 6; step++) {
        // LSTM gates: 256 threads, one gate-output each
        float acc = s2s_bih[t] + s2s_bhh[t];
#pragma unroll 4
        for (int j = 0; j < 128; j++) acc += q[j] * s2swihT[j * 256 + t];
#pragma unroll 4
        for (int j = 0; j < 64; j++) acc += hh[j] * s2swhhT[j * 256 + t];
        sgate[t] = acc;
        __syncthreads();
        if (t < 64) {
            float c = sigf(sgate[64 + t]) * ch[t] + sigf(sgate[t]) * tanhf(sgate[128 + t]);
            float h = sigf(sgate[192 + t]) * tanhf(c);
            ch[t] = c; hh[t] = h;
        }
        __syncthreads();
        // attention
        float e = 0.0f;
        if (t < 64) {
#pragma unroll 8
            for (int c = 0; c < 64; c++) e += so[t][c] * hh[c];
            red[t] = e;
        }
        __syncthreads();
        if (t < 64) {
            float mx = -1e30f;
#pragma unroll 8
            for (int n = 0; n < 64; n++) mx = fmaxf(mx, red[n]);
            sa[t] = expf(e - mx);
        }
        __syncthreads();
        if (t < 64) {
            float ssum = 0.0f, rr = 0.0f;
#pragma unroll 8
            for (int n = 0; n < 64; n++) { ssum += sa[n]; rr += sa[n] * so[n][t]; }
            q[t] = hh[t];
            q[64 + t] = rr / ssum;
        }
        __syncthreads();
    }
    // memory LSTM from zero state
    float acc = mem_bih[t] + mem_bhh[t];
#pragma unroll 4
    for (int j = 0; j < 128; j++) acc += q[j] * memwihT[j * 256 + t];
    sgate[t] = acc;
    __syncthreads();
    if (t < 64) {
        float c = sigf(sgate[t]) * tanhf(sgate[128 + t]);
        float h = sigf(sgate[192 + t]) * tanhf(c);
        hx[g * 64 + t] = h;
        int base = NT * 6;
        if (out_size >= base + 2 * NG * D) {
            out[base + g * 64 + t] = h;
            out[base + NG * 64 + g * 64 + t] = c;
        }
    }
}

// ---------------- final gather + MLP: 8 torsions per block ----------------
__global__ void __launch_bounds__(256) k_final8(
    const float* __restrict__ x, const float* __restrict__ hx,
    const int* __restrict__ nonring, const float* __restrict__ lin1T,
    const float* __restrict__ lin1b, const float* __restrict__ lin2w,
    const float* __restrict__ lin2b, float* __restrict__ out) {
    int t = threadIdx.x;
    int r0 = blockIdx.x << 3;
    __shared__ float feat[8][320];
    __shared__ float o1[8][64];
    for (int idx = t; idx < 8 * 320; idx += 256) {
        int rr = idx / 320, f = idx % 320;
        int linear = (r0 + rr) * 320 + f;
        int c = linear / (NT * 5);
        int rem = linear % (NT * 5);
        int tt = rem / 5;
        int s = rem % 5;
        float v;
        if (s == 0)
            v = hx[(tt / TPQ) * 64 + c];
        else
            v = x[(size_t)nonring[(s - 1) * NT + tt] * 64 + c];
        feat[rr][f] = v;
    }
    __syncthreads();
    int o = t & 63, tr = t >> 6;   // 4 torsions per pass, 2 passes
#pragma unroll
    for (int pass = 0; pass < 2; pass++) {
        int rr = tr + (pass << 2);
        float acc = lin1b[o];
#pragma unroll 8
        for (int f = 0; f < 320; f++) acc += feat[rr][f] * lin1T[f * 64 + o];
        o1[rr][o] = fmaxf(acc, 0.0f);
    }
    __syncthreads();
    if (t < 48) {
        int rr = t / 6, a = t % 6;
        float s = lin2b[a];
#pragma unroll 8
        for (int j = 0; j < 64; j++) s += o1[rr][j] * lin2w[a * 64 + j];
        out[(r0 + rr) * 6 + a] = s;
    }
}

// ---------------- host side (launches ONLY) ----------------
extern "C" void kernel_launch(void* const* d_in, const int* in_sizes, int n_in,
                              void* d_out, int out_size) {
    const float* x_in = (const float*)d_in[0];
    const float* edge_attr = (const float*)d_in[1];
    const int* edge_index = (const int*)d_in[2];
    const int* nonring = (const int*)d_in[4];
    int wb = (n_in >= 32) ? 8 : 6;
    const float* lin0_w = (const float*)d_in[wb + 0];
    const float* lin0_b = (const float*)d_in[wb + 1];
    const float* e1_w = (const float*)d_in[wb + 2];
    const float* e1_b = (const float*)d_in[wb + 3];
    const float* e2_w = (const float*)d_in[wb + 4];
    const float* e2_b = (const float*)d_in[wb + 5];
    const float* root_w = (const float*)d_in[wb + 6];
    const float* conv_b = (const float*)d_in[wb + 7];
    const float* gru_wih = (const float*)d_in[wb + 8];
    const float* gru_whh = (const float*)d_in[wb + 9];
    const float* gru_bih = (const float*)d_in[wb + 10];
    const float* gru_bhh = (const float*)d_in[wb + 11];
    const float* s2s_wih = (const float*)d_in[wb + 12];
    const float* s2s_whh = (const float*)d_in[wb + 13];
    const float* s2s_bih = (const float*)d_in[wb + 14];
    const float* s2s_bhh = (const float*)d_in[wb + 15];
    const float* mem_wih = (const float*)d_in[wb + 16];
    const float* mem_bih = (const float*)d_in[wb + 18];
    const float* mem_bhh = (const float*)d_in[wb + 19];
    const float* lin1_w = (const float*)d_in[wb + 20];
    const float* lin1_b = (const float*)d_in[wb + 21];
    const float* lin2_w = (const float*)d_in[wb + 22];
    const float* lin2_b = (const float*)d_in[wb + 23];
    float* out = (float*)d_out;

    float *ew, *hidden, *xb, *agg, *deg, *gruWihT, *gruWhhT;
    float *s2swihT, *s2swhhT, *memwihT, *lin1T, *hx;
    cudaGetSymbolAddress((void**)&ew, g_ew);
    cudaGetSymbolAddress((void**)&hidden, g_hidden);
    cudaGetSymbolAddress((void**)&xb, g_x);
    cudaGetSymbolAddress((void**)&agg, g_agg);
    cudaGetSymbolAddress((void**)&deg, g_deg);
    cudaGetSymbolAddress((void**)&gruWihT, g_gru_wihT);
    cudaGetSymbolAddress((void**)&gruWhhT, g_gru_whhT);
    cudaGetSymbolAddress((void**)&s2swihT, g_s2s_wihT);
    cudaGetSymbolAddress((void**)&s2swhhT, g_s2s_whhT);
    cudaGetSymbolAddress((void**)&memwihT, g_mem_wihT);
    cudaGetSymbolAddress((void**)&lin1T, g_lin1T);
    cudaGetSymbolAddress((void**)&hx, g_hx);

    // 1: edge hidden
    k_hidden<<<(NE * D + 255) / 256, 256>>>(edge_attr, e1_w, e1_b, hidden);
    // 2: node projection + zero agg/deg
    k_lin0z<<<(NNODES * D + 255) / 256, 256>>>(x_in, lin0_w, lin0_b, xb, agg, deg);
    // 3: all weight transposes
    k_prep<<<(126976 + 255) / 256, 256>>>(gru_wih, gru_whh, s2s_wih, s2s_whh, mem_wih,
                                          lin1_w, gruWihT, gruWhhT, s2swihT, s2swhhT,
                                          memwihT, lin1T);
    // 4: ew GEMM (tf32 tensor cores) — placed 4th so ncu profiles it
    k_ew_tf32<<<dim3(4096 / 64, NE / 64), 256>>>(hidden, e2_w, e2_b, ew);
    // 5: degree histogram
    k_deg<<<(NE + 255) / 256, 256>>>(edge_index, deg);

    // 6..17: 6 NNConv + GRU iterations (agg re-zeroed inside k_node)
    for (int it = 0; it < 6; it++) {
        k_msg<<<NE / 8, 256>>>(xb, edge_index, ew, agg);
        k_node<<<256, 512>>>(root_w, conv_b, agg, deg, gruWihT, gruWhhT, gru_bih,
                             gru_bhh, xb);
    }

    // 18: fused Set2Set + memory LSTM
    k_pool<<<NG, 256>>>(xb, s2swihT, s2swhhT, s2s_bih, s2s_bhh, memwihT, mem_bih,
                        mem_bhh, hx, out, out_size);
    // 19: final gather + MLP
    k_final8<<<NT / 8, 256>>>(xb, hx, nonring, lin1T, lin1_b, lin2_w, lin2_b, out);
}

// round 8
// speedup vs baseline: 1.2208x; 1.2208x over previous
#include <cuda_runtime.h>
#include <cstdint>
#include <cstdio>

#define D 64
#define NNODES 16384
#define NE 32768
#define NG 256
#define TPQ 12
#define NT (NG * TPQ)   // 3072

// ---------------- scratch (static device allocations) ----------------
__device__ float g_ew[(size_t)NE * (D * D)];   // 512 MB
__device__ float g_hidden[NE * D];
__device__ float g_x[NNODES * D];              // out == h
__device__ float g_agg[NNODES * D];
__device__ float g_m[NNODES * D];
__device__ float g_deg[NNODES];
__device__ float g_rootT[D * D];
__device__ float g_gru_wihT[64 * 192];
__device__ float g_gru_whhT[64 * 192];
__device__ float g_s2s_wihT[128 * 256];
__device__ float g_s2s_whhT[64 * 256];
__device__ float g_mem_wihT[128 * 256];
__device__ float g_lin1T[320 * 64];
__device__ float g_qstar[NG * 2 * D];
__device__ float g_hs[NG * D];
__device__ float g_cs[NG * D];
__device__ float g_hx[NG * D];

__device__ __forceinline__ float sigf(float x) { return 1.0f / (1.0f + expf(-x)); }
__device__ __forceinline__ uint32_t f2tf32(float f) {
    uint32_t r; asm("cvt.rna.tf32.f32 %0, %1;" : "=r"(r) : "f"(f)); return r;
}

// ---------------- utility kernels ----------------
__global__ void k_zero(float* p, int n) {
    int i = blockIdx.x * blockDim.x + threadIdx.x;
    if (i < n) p[i] = 0.0f;
}

__global__ void k_transpose(const float* __restrict__ in, float* __restrict__ out, int R, int C) {
    int i = blockIdx.x * blockDim.x + threadIdx.x;
    if (i < R * C) {
        int r = i / C, c = i % C;
        out[c * R + r] = in[i];
    }
}

__global__ void k_lin0(const float* __restrict__ x, const float* __restrict__ w,
                       const float* __restrict__ b, float* __restrict__ out) {
    int i = blockIdx.x * blockDim.x + threadIdx.x;
    if (i >= NNODES * D) return;
    int n = i >> 6, o = i & 63;
    float v = b[o] + x[n * 3 + 0] * w[o * 3 + 0] + x[n * 3 + 1] * w[o * 3 + 1] +
              x[n * 3 + 2] * w[o * 3 + 2];
    out[i] = fmaxf(v, 0.0f);
}

__global__ void k_hidden(const float* __restrict__ ea, const float* __restrict__ w,
                         const float* __restrict__ b, float* __restrict__ out) {
    int i = blockIdx.x * blockDim.x + threadIdx.x;
    if (i >= NE * D) return;
    int e = i >> 6, j = i & 63;
    float v = b[j];
#pragma unroll
    for (int k = 0; k < 6; k++) v += ea[e * 6 + k] * w[j * 6 + k];
    out[i] = fmaxf(v, 0.0f);
}

__global__ void k_deg(const int* __restrict__ eidx, float* __restrict__ deg) {
    int e = blockIdx.x * blockDim.x + threadIdx.x;
    if (e < NE) atomicAdd(&deg[eidx[NE + e]], 1.0f);
}

// ---------------- tf32 MMA GEMM: ew[E,4096] = hidden[E,64] @ e2_w[4096,64]^T + b2 ------
// 128x128 block tile, K staged 32 at a time (smem 2*128*36*4 = 36.9KB static).
// 256 threads = 8 warps (4m x 2n), warp tile 32x64 = 2 m-frags x 8 n-frags (m16n8k8).
// 1.5 LDS.32 per MMA (was 3.0) -> attacks the measured L1=94% bottleneck.
__global__ void __launch_bounds__(256) k_ew_tf32(
    const float* __restrict__ A, const float* __restrict__ B,
    const float* __restrict__ bias, float* __restrict__ C) {
    __shared__ uint32_t As[128 * 36];
    __shared__ uint32_t Bs[128 * 36];
    int t = threadIdx.x;
    int m0 = blockIdx.y << 7, n0 = blockIdx.x << 7;
    int lane = t & 31, w = t >> 5;
    int wm = (w >> 1) << 5;   // 0,32,64,96
    int wn = (w & 1) << 6;    // 0,64
    int grp = lane >> 2, tig = lane & 3;
    float acc[2][8][4];
#pragma unroll
    for (int a = 0; a < 2; a++)
#pragma unroll
        for (int b = 0; b < 8; b++)
#pragma unroll
            for (int c = 0; c < 4; c++) acc[a][b][c] = 0.0f;

#pragma unroll
    for (int ks = 0; ks < 2; ks++) {
        int kbase = ks << 5;
        // stage loads: 128 rows x 32 cols per operand, 4 float4 per thread each
#pragma unroll
        for (int i = t; i < 1024; i += 256) {
            int r = i >> 3, c4 = (i & 7) << 2;
            float4 va = *(const float4*)(A + (size_t)(m0 + r) * 64 + kbase + c4);
            uint32_t* da = &As[r * 36 + c4];
            da[0] = f2tf32(va.x); da[1] = f2tf32(va.y); da[2] = f2tf32(va.z); da[3] = f2tf32(va.w);
            float4 vb = *(const float4*)(B + (size_t)(n0 + r) * 64 + kbase + c4);
            uint32_t* db = &Bs[r * 36 + c4];
            db[0] = f2tf32(vb.x); db[1] = f2tf32(vb.y); db[2] = f2tf32(vb.z); db[3] = f2tf32(vb.w);
        }
        __syncthreads();
#pragma unroll
        for (int k0 = 0; k0 < 32; k0 += 8) {
            uint32_t af[2][4];
#pragma unroll
            for (int mt = 0; mt < 2; mt++) {
                int row = wm + (mt << 4) + grp;
                af[mt][0] = As[row * 36 + k0 + tig];
                af[mt][1] = As[(row + 8) * 36 + k0 + tig];
                af[mt][2] = As[row * 36 + k0 + tig + 4];
                af[mt][3] = As[(row + 8) * 36 + k0 + tig + 4];
            }
#pragma unroll
            for (int nt = 0; nt < 8; nt++) {
                int col = wn + (nt << 3) + grp;
                uint32_t b0 = Bs[col * 36 + k0 + tig];
                uint32_t b1 = Bs[col * 36 + k0 + tig + 4];
#pragma unroll
                for (int mt = 0; mt < 2; mt++) {
                    asm volatile(
                        "mma.sync.aligned.m16n8k8.row.col.f32.tf32.tf32.f32 "
                        "{%0,%1,%2,%3}, {%4,%5,%6,%7}, {%8,%9}, {%0,%1,%2,%3};\n"
                        : "+f"(acc[mt][nt][0]), "+f"(acc[mt][nt][1]),
                          "+f"(acc[mt][nt][2]), "+f"(acc[mt][nt][3])
                        : "r"(af[mt][0]), "r"(af[mt][1]), "r"(af[mt][2]), "r"(af[mt][3]),
                          "r"(b0), "r"(b1));
                }
            }
        }
        __syncthreads();
    }
#pragma unroll
    for (int mt = 0; mt < 2; mt++) {
        int row = m0 + wm + (mt << 4) + grp;
#pragma unroll
        for (int nt = 0; nt < 8; nt++) {
            int col = n0 + wn + (nt << 3) + (tig << 1);
            float b0v = bias[col], b1v = bias[col + 1];
            *(float2*)(C + (size_t)row * 4096 + col) =
                make_float2(acc[mt][nt][0] + b0v, acc[mt][nt][1] + b1v);
            *(float2*)(C + (size_t)(row + 8) * 4096 + col) =
                make_float2(acc[mt][nt][2] + b0v, acc[mt][nt][3] + b1v);
        }
    }
}

// ---------------- generic K=64 GEMM (root conv epilogue) ----------------
__global__ void k_gemm64(const float* __restrict__ A, const float* __restrict__ B,
                         const float* __restrict__ bias, float* __restrict__ C,
                         int Ncols, int epi, const float* __restrict__ agg,
                         const float* __restrict__ deg) {
    __shared__ float As[64 * 65];
    __shared__ float Bs[64 * 65];
    int t = threadIdx.x;
    int m0 = blockIdx.y << 6, n0 = blockIdx.x << 6;
    int r = t >> 4, c4 = (t & 15) << 2;
#pragma unroll
    for (int rr = 0; rr < 64; rr += 16) {
        float4 va = *(const float4*)(A + (size_t)(m0 + r + rr) * 64 + c4);
        As[(r + rr) * 65 + c4 + 0] = va.x;
        As[(r + rr) * 65 + c4 + 1] = va.y;
        As[(r + rr) * 65 + c4 + 2] = va.z;
        As[(r + rr) * 65 + c4 + 3] = va.w;
        float4 vb = *(const float4*)(B + (size_t)(n0 + r + rr) * 64 + c4);
        Bs[(r + rr) * 65 + c4 + 0] = vb.x;
        Bs[(r + rr) * 65 + c4 + 1] = vb.y;
        Bs[(r + rr) * 65 + c4 + 2] = vb.z;
        Bs[(r + rr) * 65 + c4 + 3] = vb.w;
    }
    __syncthreads();
    int tn = (t & 15) << 2;
    int tm = (t >> 4) << 2;
    float acc[4][4] = {};
#pragma unroll 8
    for (int k = 0; k < 64; k++) {
        float a0 = As[(tm + 0) * 65 + k];
        float a1 = As[(tm + 1) * 65 + k];
        float a2 = As[(tm + 2) * 65 + k];
        float a3 = As[(tm + 3) * 65 + k];
        float b0 = Bs[(tn + 0) * 65 + k];
        float b1 = Bs[(tn + 1) * 65 + k];
        float b2 = Bs[(tn + 2) * 65 + k];
        float b3 = Bs[(tn + 3) * 65 + k];
        acc[0][0] += a0 * b0; acc[0][1] += a0 * b1; acc[0][2] += a0 * b2; acc[0][3] += a0 * b3;
        acc[1][0] += a1 * b0; acc[1][1] += a1 * b1; acc[1][2] += a1 * b2; acc[1][3] += a1 * b3;
        acc[2][0] += a2 * b0; acc[2][1] += a2 * b1; acc[2][2] += a2 * b2; acc[2][3] += a2 * b3;
        acc[3][0] += a3 * b0; acc[3][1] += a3 * b1; acc[3][2] += a3 * b2; acc[3][3] += a3 * b3;
    }
#pragma unroll
    for (int i = 0; i < 4; i++) {
        int gm = m0 + tm + i;
        float vals[4];
#pragma unroll
        for (int j = 0; j < 4; j++) {
            float v = acc[i][j] + bias[n0 + tn + j];
            if (epi == 1) {
                v += agg[(size_t)gm * 64 + n0 + tn + j] * (1.0f / fmaxf(deg[gm], 1.0f));
                v = fmaxf(v, 0.0f);
            }
            vals[j] = v;
        }
        *(float4*)(C + (size_t)gm * Ncols + n0 + tn) =
            make_float4(vals[0], vals[1], vals[2], vals[3]);
    }
}

// ---------------- per-edge einsum + scatter ----------------
__global__ void k_msg(const float* __restrict__ x, const int* __restrict__ eidx,
                      const float* __restrict__ ew, float* __restrict__ agg) {
    int w = threadIdx.x >> 5, lane = threadIdx.x & 31;
    int e = blockIdx.x * 8 + w;
    int src = eidx[e], dst = eidx[NE + e];
    __shared__ float so[8][64];
    so[w][lane] = x[(size_t)src * 64 + lane];
    so[w][lane + 32] = x[(size_t)src * 64 + 32 + lane];
    __syncwarp();
    const float2* p = (const float2*)(ew + (size_t)e * 4096) + lane;
    float ax = 0.0f, ay = 0.0f;
#pragma unroll 16
    for (int i = 0; i < 64; i++) {
        float s = so[w][i];
        float2 v = p[i * 32];
        ax += s * v.x;
        ay += s * v.y;
    }
    atomicAdd(&agg[(size_t)dst * 64 + 2 * lane], ax);
    atomicAdd(&agg[(size_t)dst * 64 + 2 * lane + 1], ay);
}

// ---------------- fused GRU ----------------
__global__ void __launch_bounds__(512, 1)
k_gru_fused(const float* __restrict__ m, const float* __restrict__ wihT,
            const float* __restrict__ whhT, const float* __restrict__ bih,
            const float* __restrict__ bhh, float* __restrict__ x) {
    __shared__ float sm[64][64];
    __shared__ float sx[64][64];
    int t = threadIdx.x;
    int n0 = blockIdx.x << 6;
    for (int i = t; i < 64 * 16; i += 512) {
        int r = i >> 4, c = (i & 15) << 2;
        *(float4*)&sm[r][c] = *(const float4*)(m + (size_t)(n0 + r) * 64 + c);
        *(float4*)&sx[r][c] = *(const float4*)(x + (size_t)(n0 + r) * 64 + c);
    }
    __syncthreads();
    int o = t & 63, grp = t >> 6;
    int nb = grp << 3;
    float a0[8] = {}, a1[8] = {}, a2[8] = {}, b0[8] = {}, b1[8] = {}, b2[8] = {};
#pragma unroll 4
    for (int k = 0; k < 64; k++) {
        float wi0 = wihT[k * 192 + o];
        float wi1 = wihT[k * 192 + 64 + o];
        float wi2 = wihT[k * 192 + 128 + o];
        float wh0 = whhT[k * 192 + o];
        float wh1 = whhT[k * 192 + 64 + o];
        float wh2 = whhT[k * 192 + 128 + o];
#pragma unroll
        for (int j = 0; j < 8; j++) {
            float mv = sm[nb + j][k];
            float xv = sx[nb + j][k];
            a0[j] += mv * wi0; a1[j] += mv * wi1; a2[j] += mv * wi2;
            b0[j] += xv * wh0; b1[j] += xv * wh1; b2[j] += xv * wh2;
        }
    }
    float bi0 = bih[o], bi1 = bih[64 + o], bi2 = bih[128 + o];
    float bh0 = bhh[o], bh1 = bhh[64 + o], bh2 = bhh[128 + o];
#pragma unroll
    for (int j = 0; j < 8; j++) {
        int n = n0 + nb + j;
        float r = sigf(a0[j] + bi0 + b0[j] + bh0);
        float z = sigf(a1[j] + bi1 + b1[j] + bh1);
        float nn = tanhf(a2[j] + bi2 + r * (b2[j] + bh2));
        float h = sx[nb + j][o];
        x[(size_t)n * 64 + o] = (1.0f - z) * nn + z * h;
    }
}

// ---------------- Set2Set LSTM step ----------------
__global__ void k_s2s_lstm(const float* __restrict__ wihT, const float* __restrict__ whhT,
                           const float* __restrict__ bih, const float* __restrict__ bhh,
                           const float* __restrict__ qstar, float* __restrict__ hs,
                           float* __restrict__ cs) {
    int g = blockIdx.x, t = threadIdx.x;
    __shared__ float sq[128], sh[64];
    sq[t] = qstar[g * 128 + t];
    sq[64 + t] = qstar[g * 128 + 64 + t];
    sh[t] = hs[g * 64 + t];
    __syncthreads();
    float acc0 = bih[0 * 64 + t] + bhh[0 * 64 + t];
    float acc1 = bih[1 * 64 + t] + bhh[1 * 64 + t];
    float acc2 = bih[2 * 64 + t] + bhh[2 * 64 + t];
    float acc3 = bih[3 * 64 + t] + bhh[3 * 64 + t];
#pragma unroll 4
    for (int j = 0; j < 128; j++) {
        float q = sq[j];
        acc0 += q * wihT[j * 256 + 0 * 64 + t];
        acc1 += q * wihT[j * 256 + 1 * 64 + t];
        acc2 += q * wihT[j * 256 + 2 * 64 + t];
        acc3 += q * wihT[j * 256 + 3 * 64 + t];
    }
#pragma unroll 4
    for (int j = 0; j < 64; j++) {
        float hv = sh[j];
        acc0 += hv * whhT[j * 256 + 0 * 64 + t];
        acc1 += hv * whhT[j * 256 + 1 * 64 + t];
        acc2 += hv * whhT[j * 256 + 2 * 64 + t];
        acc3 += hv * whhT[j * 256 + 3 * 64 + t];
    }
    float c = sigf(acc1) * cs[g * 64 + t] + sigf(acc0) * tanhf(acc2);
    float h = sigf(acc3) * tanhf(c);
    cs[g * 64 + t] = c;
    hs[g * 64 + t] = h;
}

// ---------------- Set2Set attention ----------------
__global__ void k_attn(const float* __restrict__ x, const float* __restrict__ hs,
                       float* __restrict__ qstar) {
    int g = blockIdx.x, t = threadIdx.x;
    __shared__ float so[64][65];
    __shared__ float sh[64];
    __shared__ float sa[64];
    __shared__ float red[64];
    sh[t] = hs[g * 64 + t];
#pragma unroll 8
    for (int n = 0; n < 64; n++) so[n][t] = x[((size_t)g * 64 + n) * 64 + t];
    __syncthreads();
    float e = 0.0f;
#pragma unroll 8
    for (int c = 0; c < 64; c++) e += so[t][c] * sh[c];
    red[t] = e;
    __syncthreads();
    for (int s = 32; s > 0; s >>= 1) {
        if (t < s) red[t] = fmaxf(red[t], red[t + s]);
        __syncthreads();
    }
    float mx = red[0];
    __syncthreads();
    float a = expf(e - mx);
    sa[t] = a;
    red[t] = a;
    __syncthreads();
    for (int s = 32; s > 0; s >>= 1) {
        if (t < s) red[t] = red[t] + red[t + s];
        __syncthreads();
    }
    float inv = 1.0f / red[0];
    float rr = 0.0f;
#pragma unroll 8
    for (int n = 0; n < 64; n++) rr += sa[n] * so[n][t];
    qstar[g * 128 + t] = sh[t];
    qstar[g * 128 + 64 + t] = rr * inv;
}

// ---------------- memory LSTM ----------------
__global__ void k_mem_lstm(const float* __restrict__ wihT, const float* __restrict__ bih,
                           const float* __restrict__ bhh, const float* __restrict__ qstar,
                           float* __restrict__ hx, float* __restrict__ out, int out_size) {
    int g = blockIdx.x, t = threadIdx.x;
    __shared__ float sq[128];
    sq[t] = qstar[g * 128 + t];
    sq[64 + t] = qstar[g * 128 + 64 + t];
    __syncthreads();
    float acc0 = bih[0 * 64 + t] + bhh[0 * 64 + t];
    float acc1 = bih[1 * 64 + t] + bhh[1 * 64 + t];
    float acc2 = bih[2 * 64 + t] + bhh[2 * 64 + t];
    float acc3 = bih[3 * 64 + t] + bhh[3 * 64 + t];
#pragma unroll 4
    for (int j = 0; j < 128; j++) {
        float q = sq[j];
        acc0 += q * wihT[j * 256 + 0 * 64 + t];
        acc1 += q * wihT[j * 256 + 1 * 64 + t];
        acc2 += q * wihT[j * 256 + 2 * 64 + t];
        acc3 += q * wihT[j * 256 + 3 * 64 + t];
    }
    float c = sigf(acc0) * tanhf(acc2);
    float h = sigf(acc3) * tanhf(c);
    hx[g * 64 + t] = h;
    int base = NT * 6;
    if (out_size >= base + 2 * NG * D) {
        out[base + g * 64 + t] = h;
        out[base + NG * D + g * 64 + t] = c;
    }
}

// ---------------- final gather + MLP ----------------
__global__ void k_final(const float* __restrict__ x, const float* __restrict__ hx,
                        const int* __restrict__ nonring, const float* __restrict__ lin1T,
                        const float* __restrict__ lin1b, const float* __restrict__ lin2w,
                        const float* __restrict__ lin2b, float* __restrict__ out) {
    int r = blockIdx.x, t = threadIdx.x;
    __shared__ float feat[320];
    __shared__ float o1[64];
#pragma unroll
    for (int f = t; f < 320; f += 64) {
        int linear = r * 320 + f;
        int c = linear / (NT * 5);
        int rem = linear % (NT * 5);
        int tt = rem / 5;
        int s = rem % 5;
        float v;
        if (s == 0)
            v = hx[(tt / TPQ) * 64 + c];
        else
            v = x[(size_t)nonring[(s - 1) * NT + tt] * 64 + c];
        feat[f] = v;
    }
    __syncthreads();
    float acc = lin1b[t];
#pragma unroll 8
    for (int f = 0; f < 320; f++) acc += feat[f] * lin1T[f * 64 + t];
    o1[t] = fmaxf(acc, 0.0f);
    __syncthreads();
    if (t < 6) {
        float s = lin2b[t];
#pragma unroll 8
        for (int j = 0; j < 64; j++) s += o1[j] * lin2w[t * 64 + j];
        out[r * 6 + t] = s;
    }
}

// ---------------- host side (launches ONLY) ----------------
extern "C" void kernel_launch(void* const* d_in, const int* in_sizes, int n_in,
                              void* d_out, int out_size) {
    const float* x_in = (const float*)d_in[0];
    const float* edge_attr = (const float*)d_in[1];
    const int* edge_index = (const int*)d_in[2];
    const int* nonring = (const int*)d_in[4];
    int wb = (n_in >= 32) ? 8 : 6;
    const float* lin0_w = (const float*)d_in[wb + 0];
    const float* lin0_b = (const float*)d_in[wb + 1];
    const float* e1_w = (const float*)d_in[wb + 2];
    const float* e1_b = (const float*)d_in[wb + 3];
    const float* e2_w = (const float*)d_in[wb + 4];
    const float* e2_b = (const float*)d_in[wb + 5];
    const float* root_w = (const float*)d_in[wb + 6];
    const float* conv_b = (const float*)d_in[wb + 7];
    const float* gru_wih = (const float*)d_in[wb + 8];
    const float* gru_whh = (const float*)d_in[wb + 9];
    const float* gru_bih = (const float*)d_in[wb + 10];
    const float* gru_bhh = (const float*)d_in[wb + 11];
    const float* s2s_wih = (const float*)d_in[wb + 12];
    const float* s2s_whh = (const float*)d_in[wb + 13];
    const float* s2s_bih = (const float*)d_in[wb + 14];
    const float* s2s_bhh = (const float*)d_in[wb + 15];
    const float* mem_wih = (const float*)d_in[wb + 16];
    const float* mem_bih = (const float*)d_in[wb + 18];
    const float* mem_bhh = (const float*)d_in[wb + 19];
    const float* lin1_w = (const float*)d_in[wb + 20];
    const float* lin1_b = (const float*)d_in[wb + 21];
    const float* lin2_w = (const float*)d_in[wb + 22];
    const float* lin2_b = (const float*)d_in[wb + 23];
    float* out = (float*)d_out;

    float *ew, *hidden, *xb, *agg, *m, *deg, *rootT, *gruWihT, *gruWhhT;
    float *s2swihT, *s2swhhT, *memwihT, *lin1T, *qstar, *hs, *cs, *hx;
    cudaGetSymbolAddress((void**)&ew, g_ew);
    cudaGetSymbolAddress((void**)&hidden, g_hidden);
    cudaGetSymbolAddress((void**)&xb, g_x);
    cudaGetSymbolAddress((void**)&agg, g_agg);
    cudaGetSymbolAddress((void**)&m, g_m);
    cudaGetSymbolAddress((void**)&deg, g_deg);
    cudaGetSymbolAddress((void**)&rootT, g_rootT);
    cudaGetSymbolAddress((void**)&gruWihT, g_gru_wihT);
    cudaGetSymbolAddress((void**)&gruWhhT, g_gru_whhT);
    cudaGetSymbolAddress((void**)&s2swihT, g_s2s_wihT);
    cudaGetSymbolAddress((void**)&s2swhhT, g_s2s_whhT);
    cudaGetSymbolAddress((void**)&memwihT, g_mem_wihT);
    cudaGetSymbolAddress((void**)&lin1T, g_lin1T);
    cudaGetSymbolAddress((void**)&qstar, g_qstar);
    cudaGetSymbolAddress((void**)&hs, g_hs);
    cudaGetSymbolAddress((void**)&cs, g_cs);
    cudaGetSymbolAddress((void**)&hx, g_hx);

    // 1-3: projections + deg-zero
    k_hidden<<<(NE * D + 255) / 256, 256>>>(edge_attr, e1_w, e1_b, hidden);
    k_lin0<<<(NNODES * D + 255) / 256, 256>>>(x_in, lin0_w, lin0_b, xb);
    k_zero<<<(NNODES + 255) / 256, 256>>>(deg, NNODES);
    // 4: ew GEMM (tf32 tensor cores, 128x128 K-staged) — slot 4 for ncu
    k_ew_tf32<<<dim3(4096 / 128, NE / 128), 256>>>(hidden, e2_w, e2_b, ew);
    // 5: degree histogram
    k_deg<<<(NE + 255) / 256, 256>>>(edge_index, deg);
    // 6-12: weight transposes
    k_transpose<<<(64 * 64 + 255) / 256, 256>>>(root_w, rootT, 64, 64);
    k_transpose<<<(192 * 64 + 255) / 256, 256>>>(gru_wih, gruWihT, 192, 64);
    k_transpose<<<(192 * 64 + 255) / 256, 256>>>(gru_whh, gruWhhT, 192, 64);
    k_transpose<<<(256 * 128 + 255) / 256, 256>>>(s2s_wih, s2swihT, 256, 128);
    k_transpose<<<(256 * 64 + 255) / 256, 256>>>(s2s_whh, s2swhhT, 256, 64);
    k_transpose<<<(256 * 128 + 255) / 256, 256>>>(mem_wih, memwihT, 256, 128);
    k_transpose<<<(64 * 320 + 255) / 256, 256>>>(lin1_w, lin1T, 64, 320);

    // 6 NNConv + GRU iterations (R5 structure, known good)
    for (int it = 0; it < 6; it++) {
        k_zero<<<(NNODES * D + 255) / 256, 256>>>(agg, NNODES * D);
        k_msg<<<NE / 8, 256>>>(xb, edge_index, ew, agg);
        k_gemm64<<<dim3(1, NNODES / 64), 256>>>(xb, rootT, conv_b, m, 64, 1, agg, deg);
        k_gru_fused<<<256, 512>>>(m, gruWihT, gruWhhT, gru_bih, gru_bhh, xb);
    }

    // Set2Set pooling (R5 structure)
    k_zero<<<(NG * 128 + 255) / 256, 256>>>(qstar, NG * 128);
    k_zero<<<(NG * 64 + 255) / 256, 256>>>(hs, NG * 64);
    k_zero<<<(NG * 64 + 255) / 256, 256>>>(cs, NG * 64);
    for (int s = 0; s < 6; s++) {
        k_s2s_lstm<<<NG, 64>>>(s2swihT, s2swhhT, s2s_bih, s2s_bhh, qstar, hs, cs);
        k_attn<<<NG, 64>>>(xb, hs, qstar);
    }

    // memory LSTM + final MLP
    k_mem_lstm<<<NG, 64>>>(memwihT, mem_bih, mem_bhh, qstar, hx, out, out_size);
    k_final<<<NT, 64>>>(xb, hx, nonring, lin1T, lin1_b, lin2_w, lin2_b, out);
}

// round 12
// speedup vs baseline: 1.2269x; 1.0050x over previous
#include <cuda_runtime.h>
#include <cstdint>
#include <cstdio>

#define D 64
#define NNODES 16384
#define NE 32768
#define NG 256
#define TPQ 12
#define NT (NG * TPQ)   // 3072

// ---------------- scratch (static device allocations) ----------------
__device__ float g_ew[(size_t)NE * (D * D)];   // 512 MB
__device__ float g_hidden[NE * D];
__device__ float g_x[NNODES * D];              // out == h
__device__ float g_agg[NNODES * D];
__device__ float g_m[NNODES * D];
__device__ float g_deg[NNODES];
__device__ float g_rootT[D * D];
__device__ float g_gru_wihT[64 * 192];
__device__ float g_gru_whhT[64 * 192];
__device__ float g_s2s_wihT[128 * 256];
__device__ float g_s2s_whhT[64 * 256];
__device__ float g_mem_wihT[128 * 256];
__device__ float g_lin1T[320 * 64];
__device__ float g_qstar[NG * 2 * D];
__device__ float g_hs[NG * D];
__device__ float g_cs[NG * D];
__device__ float g_hx[NG * D];

__device__ __forceinline__ float sigf(float x) { return 1.0f / (1.0f + expf(-x)); }
__device__ __forceinline__ uint32_t f2tf32(float f) {
    uint32_t r; asm("cvt.rna.tf32.f32 %0, %1;" : "=r"(r) : "f"(f)); return r;
}

// ---------------- utility kernels ----------------
__global__ void k_zero(float* p, int n) {
    int i = blockIdx.x * blockDim.x + threadIdx.x;
    if (i < n) p[i] = 0.0f;
}

__global__ void k_transpose(const float* __restrict__ in, float* __restrict__ out, int R, int C) {
    int i = blockIdx.x * blockDim.x + threadIdx.x;
    if (i < R * C) {
        int r = i / C, c = i % C;
        out[c * R + r] = in[i];
    }
}

__global__ void k_lin0(const float* __restrict__ x, const float* __restrict__ w,
                       const float* __restrict__ b, float* __restrict__ out) {
    int i = blockIdx.x * blockDim.x + threadIdx.x;
    if (i >= NNODES * D) return;
    int n = i >> 6, o = i & 63;
    float v = b[o] + x[n * 3 + 0] * w[o * 3 + 0] + x[n * 3 + 1] * w[o * 3 + 1] +
              x[n * 3 + 2] * w[o * 3 + 2];
    out[i] = fmaxf(v, 0.0f);
}

__global__ void k_hidden(const float* __restrict__ ea, const float* __restrict__ w,
                         const float* __restrict__ b, float* __restrict__ out) {
    int i = blockIdx.x * blockDim.x + threadIdx.x;
    if (i >= NE * D) return;
    int e = i >> 6, j = i & 63;
    float v = b[j];
#pragma unroll
    for (int k = 0; k < 6; k++) v += ea[e * 6 + k] * w[j * 6 + k];
    out[i] = fmaxf(v, 0.0f);
}

__global__ void k_deg(const int* __restrict__ eidx, float* __restrict__ deg) {
    int e = blockIdx.x * blockDim.x + threadIdx.x;
    if (e < NE) atomicAdd(&deg[eidx[NE + e]], 1.0f);
}

// ---------------- tf32 MMA GEMM: ew[E,4096] = hidden[E,64] @ e2_w[4096,64]^T + b2 ------
// 128x64 block tile, K staged 32 at a time (smem (128+64)*36*4 = 27.6KB static).
// 256 threads = 8 warps (4m x 2n), warp tile 32x32 = 2 m-frags x 4 n-frags (m16n8k8).
// acc = 32 regs/thread -> ~90 regs total -> 2 CTAs/SM (was 1 @ 160 regs, occ 12.3%).
__global__ void __launch_bounds__(256, 2) k_ew_tf32(
    const float* __restrict__ A, const float* __restrict__ B,
    const float* __restrict__ bias, float* __restrict__ C) {
    __shared__ uint32_t As[128 * 36];
    __shared__ uint32_t Bs[64 * 36];
    int t = threadIdx.x;
    int m0 = blockIdx.y << 7, n0 = blockIdx.x << 6;
    int lane = t & 31, w = t >> 5;
    int wm = (w >> 1) << 5;   // 0,32,64,96
    int wn = (w & 1) << 5;    // 0,32
    int grp = lane >> 2, tig = lane & 3;
    float acc[2][4][4];
#pragma unroll
    for (int a = 0; a < 2; a++)
#pragma unroll
        for (int b = 0; b < 4; b++)
#pragma unroll
            for (int c = 0; c < 4; c++) acc[a][b][c] = 0.0f;

#pragma unroll
    for (int ks = 0; ks < 2; ks++) {
        int kbase = ks << 5;
        // stage A: 128 rows x 32 cols (4 float4/thread)
#pragma unroll
        for (int i = t; i < 1024; i += 256) {
            int r = i >> 3, c4 = (i & 7) << 2;
            float4 va = *(const float4*)(A + (size_t)(m0 + r) * 64 + kbase + c4);
            uint32_t* da = &As[r * 36 + c4];
            da[0] = f2tf32(va.x); da[1] = f2tf32(va.y); da[2] = f2tf32(va.z); da[3] = f2tf32(va.w);
        }
        // stage B: 64 rows x 32 cols (2 float4/thread)
#pragma unroll
        for (int i = t; i < 512; i += 256) {
            int r = i >> 3, c4 = (i & 7) << 2;
            float4 vb = *(const float4*)(B + (size_t)(n0 + r) * 64 + kbase + c4);
            uint32_t* db = &Bs[r * 36 + c4];
            db[0] = f2tf32(vb.x); db[1] = f2tf32(vb.y); db[2] = f2tf32(vb.z); db[3] = f2tf32(vb.w);
        }
        __syncthreads();
#pragma unroll
        for (int k0 = 0; k0 < 32; k0 += 8) {
            uint32_t af[2][4];
#pragma unroll
            for (int mt = 0; mt < 2; mt++) {
                int row = wm + (mt << 4) + grp;
                af[mt][0] = As[row * 36 + k0 + tig];
                af[mt][1] = As[(row + 8) * 36 + k0 + tig];
                af[mt][2] = As[row * 36 + k0 + tig + 4];
                af[mt][3] = As[(row + 8) * 36 + k0 + tig + 4];
            }
#pragma unroll
            for (int nt = 0; nt < 4; nt++) {
                int col = wn + (nt << 3) + grp;
                uint32_t b0 = Bs[col * 36 + k0 + tig];
                uint32_t b1 = Bs[col * 36 + k0 + tig + 4];
#pragma unroll
                for (int mt = 0; mt < 2; mt++) {
                    asm volatile(
                        "mma.sync.aligned.m16n8k8.row.col.f32.tf32.tf32.f32 "
                        "{%0,%1,%2,%3}, {%4,%5,%6,%7}, {%8,%9}, {%0,%1,%2,%3};\n"
                        : "+f"(acc[mt][nt][0]), "+f"(acc[mt][nt][1]),
                          "+f"(acc[mt][nt][2]), "+f"(acc[mt][nt][3])
                        : "r"(af[mt][0]), "r"(af[mt][1]), "r"(af[mt][2]), "r"(af[mt][3]),
                          "r"(b0), "r"(b1));
                }
            }
        }
        __syncthreads();
    }
#pragma unroll
    for (int mt = 0; mt < 2; mt++) {
        int row = m0 + wm + (mt << 4) + grp;
#pragma unroll
        for (int nt = 0; nt < 4; nt++) {
            int col = n0 + wn + (nt << 3) + (tig << 1);
            float b0v = bias[col], b1v = bias[col + 1];
            *(float2*)(C + (size_t)row * 4096 + col) =
                make_float2(acc[mt][nt][0] + b0v, acc[mt][nt][1] + b1v);
            *(float2*)(C + (size_t)(row + 8) * 4096 + col) =
                make_float2(acc[mt][nt][2] + b0v, acc[mt][nt][3] + b1v);
        }
    }
}

// ---------------- generic K=64 GEMM (root conv epilogue) ----------------
__global__ void k_gemm64(const float* __restrict__ A, const float* __restrict__ B,
                         const float* __restrict__ bias, float* __restrict__ C,
                         int Ncols, int epi, const float* __restrict__ agg,
                         const float* __restrict__ deg) {
    __shared__ float As[64 * 65];
    __shared__ float Bs[64 * 65];
    int t = threadIdx.x;
    int m0 = blockIdx.y << 6, n0 = blockIdx.x << 6;
    int r = t >> 4, c4 = (t & 15) << 2;
#pragma unroll
    for (int rr = 0; rr < 64; rr += 16) {
        float4 va = *(const float4*)(A + (size_t)(m0 + r + rr) * 64 + c4);
        As[(r + rr) * 65 + c4 + 0] = va.x;
        As[(r + rr) * 65 + c4 + 1] = va.y;
        As[(r + rr) * 65 + c4 + 2] = va.z;
        As[(r + rr) * 65 + c4 + 3] = va.w;
        float4 vb = *(const float4*)(B + (size_t)(n0 + r + rr) * 64 + c4);
        Bs[(r + rr) * 65 + c4 + 0] = vb.x;
        Bs[(r + rr) * 65 + c4 + 1] = vb.y;
        Bs[(r + rr) * 65 + c4 + 2] = vb.z;
        Bs[(r + rr) * 65 + c4 + 3] = vb.w;
    }
    __syncthreads();
    int tn = (t & 15) << 2;
    int tm = (t >> 4) << 2;
    float acc[4][4] = {};
#pragma unroll 8
    for (int k = 0; k < 64; k++) {
        float a0 = As[(tm + 0) * 65 + k];
        float a1 = As[(tm + 1) * 65 + k];
        float a2 = As[(tm + 2) * 65 + k];
        float a3 = As[(tm + 3) * 65 + k];
        float b0 = Bs[(tn + 0) * 65 + k];
        float b1 = Bs[(tn + 1) * 65 + k];
        float b2 = Bs[(tn + 2) * 65 + k];
        float b3 = Bs[(tn + 3) * 65 + k];
        acc[0][0] += a0 * b0; acc[0][1] += a0 * b1; acc[0][2] += a0 * b2; acc[0][3] += a0 * b3;
        acc[1][0] += a1 * b0; acc[1][1] += a1 * b1; acc[1][2] += a1 * b2; acc[1][3] += a1 * b3;
        acc[2][0] += a2 * b0; acc[2][1] += a2 * b1; acc[2][2] += a2 * b2; acc[2][3] += a2 * b3;
        acc[3][0] += a3 * b0; acc[3][1] += a3 * b1; acc[3][2] += a3 * b2; acc[3][3] += a3 * b3;
    }
#pragma unroll
    for (int i = 0; i < 4; i++) {
        int gm = m0 + tm + i;
        float vals[4];
#pragma unroll
        for (int j = 0; j < 4; j++) {
            float v = acc[i][j] + bias[n0 + tn + j];
            if (epi == 1) {
                v += agg[(size_t)gm * 64 + n0 + tn + j] * (1.0f / fmaxf(deg[gm], 1.0f));
                v = fmaxf(v, 0.0f);
            }
            vals[j] = v;
        }
        *(float4*)(C + (size_t)gm * Ncols + n0 + tn) =
            make_float4(vals[0], vals[1], vals[2], vals[3]);
    }
}

// ---------------- per-edge einsum + scatter (float4 loads, half-warp row split) -------
// Warp handles one edge. Iteration j loads rows 2j (lanes 0-15) and 2j+1 (lanes 16-31)
// as LDG.128; partial sums combined via shfl_xor(16); lanes 0-15 issue 4 atomics each.
__global__ void k_msg(const float* __restrict__ x, const int* __restrict__ eidx,
                      const float* __restrict__ ew, float* __restrict__ agg) {
    int w = threadIdx.x >> 5, lane = threadIdx.x & 31;
    int e = blockIdx.x * 8 + w;
    int src = eidx[e], dst = eidx[NE + e];
    __shared__ float so[8][64];
    so[w][lane] = x[(size_t)src * 64 + lane];
    so[w][lane + 32] = x[(size_t)src * 64 + 32 + lane];
    __syncwarp();
    int half = lane >> 4;       // 0: even rows, 1: odd rows
    int cq = lane & 15;         // column quad: cols [4cq, 4cq+4)
    const float4* p = (const float4*)(ew + (size_t)e * 4096) + cq;
    float a0 = 0.0f, a1 = 0.0f, a2 = 0.0f, a3 = 0.0f;
#pragma unroll 16
    for (int j = 0; j < 32; j++) {
        int row = (j << 1) + half;
        float s = so[w][row];
        float4 v = p[row << 4];
        a0 += s * v.x; a1 += s * v.y; a2 += s * v.z; a3 += s * v.w;
    }
    a0 += __shfl_xor_sync(0xffffffffu, a0, 16);
    a1 += __shfl_xor_sync(0xffffffffu, a1, 16);
    a2 += __shfl_xor_sync(0xffffffffu, a2, 16);
    a3 += __shfl_xor_sync(0xffffffffu, a3, 16);
    if (half == 0) {
        float* dp = &agg[(size_t)dst * 64 + (cq << 2)];
        atomicAdd(dp + 0, a0);
        atomicAdd(dp + 1, a1);
        atomicAdd(dp + 2, a2);
        atomicAdd(dp + 3, a3);
    }
}

// ---------------- fused GRU ----------------
__global__ void __launch_bounds__(512, 1)
k_gru_fused(const float* __restrict__ m, const float* __restrict__ wihT,
            const float* __restrict__ whhT, const float* __restrict__ bih,
            const float* __restrict__ bhh, float* __restrict__ x) {
    __shared__ float sm[64][64];
    __shared__ float sx[64][64];
    int t = threadIdx.x;
    int n0 = blockIdx.x << 6;
    for (int i = t; i < 64 * 16; i += 512) {
        int r = i >> 4, c = (i & 15) << 2;
        *(float4*)&sm[r][c] = *(const float4*)(m + (size_t)(n0 + r) * 64 + c);
        *(float4*)&sx[r][c] = *(const float4*)(x + (size_t)(n0 + r) * 64 + c);
    }
    __syncthreads();
    int o = t & 63, grp = t >> 6;
    int nb = grp << 3;
    float a0[8] = {}, a1[8] = {}, a2[8] = {}, b0[8] = {}, b1[8] = {}, b2[8] = {};
#pragma unroll 4
    for (int k = 0; k < 64; k++) {
        float wi0 = wihT[k * 192 + o];
        float wi1 = wihT[k * 192 + 64 + o];
        float wi2 = wihT[k * 192 + 128 + o];
        float wh0 = whhT[k * 192 + o];
        float wh1 = whhT[k * 192 + 64 + o];
        float wh2 = whhT[k * 192 + 128 + o];
#pragma unroll
        for (int j = 0; j < 8; j++) {
            float mv = sm[nb + j][k];
            float xv = sx[nb + j][k];
            a0[j] += mv * wi0; a1[j] += mv * wi1; a2[j] += mv * wi2;
            b0[j] += xv * wh0; b1[j] += xv * wh1; b2[j] += xv * wh2;
        }
    }
    float bi0 = bih[o], bi1 = bih[64 + o], bi2 = bih[128 + o];
    float bh0 = bhh[o], bh1 = bhh[64 + o], bh2 = bhh[128 + o];
#pragma unroll
    for (int j = 0; j < 8; j++) {
        int n = n0 + nb + j;
        float r = sigf(a0[j] + bi0 + b0[j] + bh0);
        float z = sigf(a1[j] + bi1 + b1[j] + bh1);
        float nn = tanhf(a2[j] + bi2 + r * (b2[j] + bh2));
        float h = sx[nb + j][o];
        x[(size_t)n * 64 + o] = (1.0f - z) * nn + z * h;
    }
}

// ---------------- Set2Set LSTM step ----------------
__global__ void k_s2s_lstm(const float* __restrict__ wihT, const float* __restrict__ whhT,
                           const float* __restrict__ bih, const float* __restrict__ bhh,
                           const float* __restrict__ qstar, float* __restrict__ hs,
                           float* __restrict__ cs) {
    int g = blockIdx.x, t = threadIdx.x;
    __shared__ float sq[128], sh[64];
    sq[t] = qstar[g * 128 + t];
    sq[64 + t] = qstar[g * 128 + 64 + t];
    sh[t] = hs[g * 64 + t];
    __syncthreads();
    float acc0 = bih[0 * 64 + t] + bhh[0 * 64 + t];
    float acc1 = bih[1 * 64 + t] + bhh[1 * 64 + t];
    float acc2 = bih[2 * 64 + t] + bhh[2 * 64 + t];
    float acc3 = bih[3 * 64 + t] + bhh[3 * 64 + t];
#pragma unroll 4
    for (int j = 0; j < 128; j++) {
        float q = sq[j];
        acc0 += q * wihT[j * 256 + 0 * 64 + t];
        acc1 += q * wihT[j * 256 + 1 * 64 + t];
        acc2 += q * wihT[j * 256 + 2 * 64 + t];
        acc3 += q * wihT[j * 256 + 3 * 64 + t];
    }
#pragma unroll 4
    for (int j = 0; j < 64; j++) {
        float hv = sh[j];
        acc0 += hv * whhT[j * 256 + 0 * 64 + t];
        acc1 += hv * whhT[j * 256 + 1 * 64 + t];
        acc2 += hv * whhT[j * 256 + 2 * 64 + t];
        acc3 += hv * whhT[j * 256 + 3 * 64 + t];
    }
    float c = sigf(acc1) * cs[g * 64 + t] + sigf(acc0) * tanhf(acc2);
    float h = sigf(acc3) * tanhf(c);
    cs[g * 64 + t] = c;
    hs[g * 64 + t] = h;
}

// ---------------- Set2Set attention ----------------
__global__ void k_attn(const float* __restrict__ x, const float* __restrict__ hs,
                       float* __restrict__ qstar) {
    int g = blockIdx.x, t = threadIdx.x;
    __shared__ float so[64][65];
    __shared__ float sh[64];
    __shared__ float sa[64];
    __shared__ float red[64];
    sh[t] = hs[g * 64 + t];
#pragma unroll 8
    for (int n = 0; n < 64; n++) so[n][t] = x[((size_t)g * 64 + n) * 64 + t];
    __syncthreads();
    float e = 0.0f;
#pragma unroll 8
    for (int c = 0; c < 64; c++) e += so[t][c] * sh[c];
    red[t] = e;
    __syncthreads();
    for (int s = 32; s > 0; s >>= 1) {
        if (t < s) red[t] = fmaxf(red[t], red[t + s]);
        __syncthreads();
    }
    float mx = red[0];
    __syncthreads();
    float a = expf(e - mx);
    sa[t] = a;
    red[t] = a;
    __syncthreads();
    for (int s = 32; s > 0; s >>= 1) {
        if (t < s) red[t] = red[t] + red[t + s];
        __syncthreads();
    }
    float inv = 1.0f / red[0];
    float rr = 0.0f;
#pragma unroll 8
    for (int n = 0; n < 64; n++) rr += sa[n] * so[n][t];
    qstar[g * 128 + t] = sh[t];
    qstar[g * 128 + 64 + t] = rr * inv;
}

// ---------------- memory LSTM ----------------
__global__ void k_mem_lstm(const float* __restrict__ wihT, const float* __restrict__ bih,
                           const float* __restrict__ bhh, const float* __restrict__ qstar,
                           float* __restrict__ hx, float* __restrict__ out, int out_size) {
    int g = blockIdx.x, t = threadIdx.x;
    __shared__ float sq[128];
    sq[t] = qstar[g * 128 + t];
    sq[64 + t] = qstar[g * 128 + 64 + t];
    __syncthreads();
    float acc0 = bih[0 * 64 + t] + bhh[0 * 64 + t];
    float acc1 = bih[1 * 64 + t] + bhh[1 * 64 + t];
    float acc2 = bih[2 * 64 + t] + bhh[2 * 64 + t];
    float acc3 = bih[3 * 64 + t] + bhh[3 * 64 + t];
#pragma unroll 4
    for (int j = 0; j < 128; j++) {
        float q = sq[j];
        acc0 += q * wihT[j * 256 + 0 * 64 + t];
        acc1 += q * wihT[j * 256 + 1 * 64 + t];
        acc2 += q * wihT[j * 256 + 2 * 64 + t];
        acc3 += q * wihT[j * 256 + 3 * 64 + t];
    }
    float c = sigf(acc0) * tanhf(acc2);
    float h = sigf(acc3) * tanhf(c);
    hx[g * 64 + t] = h;
    int base = NT * 6;
    if (out_size >= base + 2 * NG * D) {
        out[base + g * 64 + t] = h;
        out[base + NG * D + g * 64 + t] = c;
    }
}

// ---------------- final gather + MLP ----------------
__global__ void k_final(const float* __restrict__ x, const float* __restrict__ hx,
                        const int* __restrict__ nonring, const float* __restrict__ lin1T,
                        const float* __restrict__ lin1b, const float* __restrict__ lin2w,
                        const float* __restrict__ lin2b, float* __restrict__ out) {
    int r = blockIdx.x, t = threadIdx.x;
    __shared__ float feat[320];
    __shared__ float o1[64];
#pragma unroll
    for (int f = t; f < 320; f += 64) {
        int linear = r * 320 + f;
        int c = linear / (NT * 5);
        int rem = linear % (NT * 5);
        int tt = rem / 5;
        int s = rem % 5;
        float v;
        if (s == 0)
            v = hx[(tt / TPQ) * 64 + c];
        else
            v = x[(size_t)nonring[(s - 1) * NT + tt] * 64 + c];
        feat[f] = v;
    }
    __syncthreads();
    float acc = lin1b[t];
#pragma unroll 8
    for (int f = 0; f < 320; f++) acc += feat[f] * lin1T[f * 64 + t];
    o1[t] = fmaxf(acc, 0.0f);
    __syncthreads();
    if (t < 6) {
        float s = lin2b[t];
#pragma unroll 8
        for (int j = 0; j < 64; j++) s += o1[j] * lin2w[t * 64 + j];
        out[r * 6 + t] = s;
    }
}

// ---------------- host side (launches ONLY) ----------------
extern "C" void kernel_launch(void* const* d_in, const int* in_sizes, int n_in,
                              void* d_out, int out_size) {
    const float* x_in = (const float*)d_in[0];
    const float* edge_attr = (const float*)d_in[1];
    const int* edge_index = (const int*)d_in[2];
    const int* nonring = (const int*)d_in[4];
    int wb = (n_in >= 32) ? 8 : 6;
    const float* lin0_w = (const float*)d_in[wb + 0];
    const float* lin0_b = (const float*)d_in[wb + 1];
    const float* e1_w = (const float*)d_in[wb + 2];
    const float* e1_b = (const float*)d_in[wb + 3];
    const float* e2_w = (const float*)d_in[wb + 4];
    const float* e2_b = (const float*)d_in[wb + 5];
    const float* root_w = (const float*)d_in[wb + 6];
    const float* conv_b = (const float*)d_in[wb + 7];
    const float* gru_wih = (const float*)d_in[wb + 8];
    const float* gru_whh = (const float*)d_in[wb + 9];
    const float* gru_bih = (const float*)d_in[wb + 10];
    const float* gru_bhh = (const float*)d_in[wb + 11];
    const float* s2s_wih = (const float*)d_in[wb + 12];
    const float* s2s_whh = (const float*)d_in[wb + 13];
    const float* s2s_bih = (const float*)d_in[wb + 14];
    const float* s2s_bhh = (const float*)d_in[wb + 15];
    const float* mem_wih = (const float*)d_in[wb + 16];
    const float* mem_bih = (const float*)d_in[wb + 18];
    const float* mem_bhh = (const float*)d_in[wb + 19];
    const float* lin1_w = (const float*)d_in[wb + 20];
    const float* lin1_b = (const float*)d_in[wb + 21];
    const float* lin2_w = (const float*)d_in[wb + 22];
    const float* lin2_b = (const float*)d_in[wb + 23];
    float* out = (float*)d_out;

    float *ew, *hidden, *xb, *agg, *m, *deg, *rootT, *gruWihT, *gruWhhT;
    float *s2swihT, *s2swhhT, *memwihT, *lin1T, *qstar, *hs, *cs, *hx;
    cudaGetSymbolAddress((void**)&ew, g_ew);
    cudaGetSymbolAddress((void**)&hidden, g_hidden);
    cudaGetSymbolAddress((void**)&xb, g_x);
    cudaGetSymbolAddress((void**)&agg, g_agg);
    cudaGetSymbolAddress((void**)&m, g_m);
    cudaGetSymbolAddress((void**)&deg, g_deg);
    cudaGetSymbolAddress((void**)&rootT, g_rootT);
    cudaGetSymbolAddress((void**)&gruWihT, g_gru_wihT);
    cudaGetSymbolAddress((void**)&gruWhhT, g_gru_whhT);
    cudaGetSymbolAddress((void**)&s2swihT, g_s2s_wihT);
    cudaGetSymbolAddress((void**)&s2swhhT, g_s2s_whhT);
    cudaGetSymbolAddress((void**)&memwihT, g_mem_wihT);
    cudaGetSymbolAddress((void**)&lin1T, g_lin1T);
    cudaGetSymbolAddress((void**)&qstar, g_qstar);
    cudaGetSymbolAddress((void**)&hs, g_hs);
    cudaGetSymbolAddress((void**)&cs, g_cs);
    cudaGetSymbolAddress((void**)&hx, g_hx);

    // 1-3: projections + deg-zero
    k_hidden<<<(NE * D + 255) / 256, 256>>>(edge_attr, e1_w, e1_b, hidden);
    k_lin0<<<(NNODES * D + 255) / 256, 256>>>(x_in, lin0_w, lin0_b, xb);
    k_zero<<<(NNODES + 255) / 256, 256>>>(deg, NNODES);
    // 4: ew GEMM (tf32 tensor cores, 128x64 K-staged, 2 CTA/SM) — slot 4 for ncu
    k_ew_tf32<<<dim3(4096 / 64, NE / 128), 256>>>(hidden, e2_w, e2_b, ew);
    // 5: degree histogram
    k_deg<<<(NE + 255) / 256, 256>>>(edge_index, deg);
    // 6-12: weight transposes
    k_transpose<<<(64 * 64 + 255) / 256, 256>>>(root_w, rootT, 64, 64);
    k_transpose<<<(192 * 64 + 255) / 256, 256>>>(gru_wih, gruWihT, 192, 64);
    k_transpose<<<(192 * 64 + 255) / 256, 256>>>(gru_whh, gruWhhT, 192, 64);
    k_transpose<<<(256 * 128 + 255) / 256, 256>>>(s2s_wih, s2swihT, 256, 128);
    k_transpose<<<(256 * 64 + 255) / 256, 256>>>(s2s_whh, s2swhhT, 256, 64);
    k_transpose<<<(256 * 128 + 255) / 256, 256>>>(mem_wih, memwihT, 256, 128);
    k_transpose<<<(64 * 320 + 255) / 256, 256>>>(lin1_w, lin1T, 64, 320);

    // 6 NNConv + GRU iterations
    for (int it = 0; it < 6; it++) {
        k_zero<<<(NNODES * D + 255) / 256, 256>>>(agg, NNODES * D);
        k_msg<<<NE / 8, 256>>>(xb, edge_index, ew, agg);
        k_gemm64<<<dim3(1, NNODES / 64), 256>>>(xb, rootT, conv_b, m, 64, 1, agg, deg);
        k_gru_fused<<<256, 512>>>(m, gruWihT, gruWhhT, gru_bih, gru_bhh, xb);
    }

    // Set2Set pooling
    k_zero<<<(NG * 128 + 255) / 256, 256>>>(qstar, NG * 128);
    k_zero<<<(NG * 64 + 255) / 256, 256>>>(hs, NG * 64);
    k_zero<<<(NG * 64 + 255) / 256, 256>>>(cs, NG * 64);
    for (int s = 0; s < 6; s++) {
        k_s2s_lstm<<<NG, 64>>>(s2swihT, s2swhhT, s2s_bih, s2s_bhh, qstar, hs, cs);
        k_attn<<<NG, 64>>>(xb, hs, qstar);
    }

    // memory LSTM + final MLP
    k_mem_lstm<<<NG, 64>>>(memwihT, mem_bih, mem_bhh, qstar, hx, out, out_size);
    k_final<<<NT, 64>>>(xb, hx, nonring, lin1T, lin1_b, lin2_w, lin2_b, out);
}

// round 14
// speedup vs baseline: 1.4345x; 1.1692x over previous
#include <cuda_runtime.h>
#include <cstdint>
#include <cstdio>

#define D 64
#define NNODES 16384
#define NE 32768
#define NG 256
#define TPQ 12
#define NT (NG * TPQ)   // 3072

// ---------------- scratch (static device allocations) ----------------
__device__ float g_ew[(size_t)NE * (D * D)];   // 512 MB
__device__ float g_hidden[NE * D];
__device__ float g_x[NNODES * D];              // out == h
__device__ float g_agg[NNODES * D];
__device__ float g_m[NNODES * D];
__device__ float g_deg[NNODES];
__device__ float g_rootT[D * D];
__device__ float g_gru_wihT[64 * 192];
__device__ float g_gru_whhT[64 * 192];
__device__ float g_s2s_wihT[128 * 256];
__device__ float g_s2s_whhT[64 * 256];
__device__ float g_mem_wihT[128 * 256];
__device__ float g_lin1T[320 * 64];
__device__ float g_hx[NG * D];

__device__ __forceinline__ float sigf(float x) { return 1.0f / (1.0f + expf(-x)); }
__device__ __forceinline__ uint32_t f2tf32(float f) {
    uint32_t r; asm("cvt.rna.tf32.f32 %0, %1;" : "=r"(r) : "f"(f)); return r;
}

// ---------------- prologue kernels ----------------
__global__ void k_hidden(const float* __restrict__ ea, const float* __restrict__ w,
                         const float* __restrict__ b, float* __restrict__ out) {
    int i = blockIdx.x * blockDim.x + threadIdx.x;
    if (i >= NE * D) return;
    int e = i >> 6, j = i & 63;
    float v = b[j];
#pragma unroll
    for (int k = 0; k < 6; k++) v += ea[e * 6 + k] * w[j * 6 + k];
    out[i] = fmaxf(v, 0.0f);
}

// x = relu(pos @ lin0_w^T + b); also zero agg and deg
__global__ void k_lin0z(const float* __restrict__ x, const float* __restrict__ w,
                        const float* __restrict__ b, float* __restrict__ out,
                        float* __restrict__ agg, float* __restrict__ deg) {
    int i = blockIdx.x * blockDim.x + threadIdx.x;
    if (i >= NNODES * D) return;
    int n = i >> 6, o = i & 63;
    float v = b[o] + x[n * 3 + 0] * w[o * 3 + 0] + x[n * 3 + 1] * w[o * 3 + 1] +
              x[n * 3 + 2] * w[o * 3 + 2];
    out[i] = fmaxf(v, 0.0f);
    agg[i] = 0.0f;
    if (o == 0) deg[n] = 0.0f;
}

__global__ void k_transpose(const float* __restrict__ in, float* __restrict__ out, int R, int C) {
    int i = blockIdx.x * blockDim.x + threadIdx.x;
    if (i < R * C) {
        int r = i / C, c = i % C;
        out[c * R + r] = in[i];
    }
}

// all remaining weight transposes in one launch (R6-verified)
__global__ void k_prep(const float* __restrict__ gru_wih, const float* __restrict__ gru_whh,
                       const float* __restrict__ s2s_wih, const float* __restrict__ s2s_whh,
                       const float* __restrict__ mem_wih, const float* __restrict__ lin1_w,
                       float* __restrict__ gruWihT, float* __restrict__ gruWhhT,
                       float* __restrict__ s2swihT, float* __restrict__ s2swhhT,
                       float* __restrict__ memwihT, float* __restrict__ lin1T) {
    int i = blockIdx.x * blockDim.x + threadIdx.x;
    if (i < 12288) {                      // gru_wih [192,64] -> [64,192]
        int r = i / 64, c = i % 64;
        gruWihT[c * 192 + r] = gru_wih[i];
    } else if (i < 24576) {               // gru_whh
        int j = i - 12288;
        int r = j / 64, c = j % 64;
        gruWhhT[c * 192 + r] = gru_whh[j];
    } else if (i < 57344) {               // s2s_wih [256,128] -> [128,256]
        int j = i - 24576;
        int r = j / 128, c = j % 128;
        s2swihT[c * 256 + r] = s2s_wih[j];
    } else if (i < 73728) {               // s2s_whh [256,64] -> [64,256]
        int j = i - 57344;
        int r = j / 64, c = j % 64;
        s2swhhT[c * 256 + r] = s2s_whh[j];
    } else if (i < 106496) {              // mem_wih [256,128] -> [128,256]
        int j = i - 73728;
        int r = j / 128, c = j % 128;
        memwihT[c * 256 + r] = mem_wih[j];
    } else if (i < 126976) {              // lin1_w [64,320] -> [320,64]
        int j = i - 106496;
        int r = j / 320, c = j % 320;
        lin1T[c * 64 + r] = lin1_w[j];
    }
}

__global__ void k_deg(const int* __restrict__ eidx, float* __restrict__ deg) {
    int e = blockIdx.x * blockDim.x + threadIdx.x;
    if (e < NE) atomicAdd(&deg[eidx[NE + e]], 1.0f);
}

// ---------------- tf32 MMA GEMM: ew[E,4096] = hidden[E,64] @ e2_w[4096,64]^T + b2 ------
__global__ void __launch_bounds__(256, 2) k_ew_tf32(
    const float* __restrict__ A, const float* __restrict__ B,
    const float* __restrict__ bias, float* __restrict__ C) {
    __shared__ uint32_t As[128 * 36];
    __shared__ uint32_t Bs[64 * 36];
    int t = threadIdx.x;
    int m0 = blockIdx.y << 7, n0 = blockIdx.x << 6;
    int lane = t & 31, w = t >> 5;
    int wm = (w >> 1) << 5;
    int wn = (w & 1) << 5;
    int grp = lane >> 2, tig = lane & 3;
    float acc[2][4][4];
#pragma unroll
    for (int a = 0; a < 2; a++)
#pragma unroll
        for (int b = 0; b < 4; b++)
#pragma unroll
            for (int c = 0; c < 4; c++) acc[a][b][c] = 0.0f;

#pragma unroll
    for (int ks = 0; ks < 2; ks++) {
        int kbase = ks << 5;
#pragma unroll
        for (int i = t; i < 1024; i += 256) {
            int r = i >> 3, c4 = (i & 7) << 2;
            float4 va = *(const float4*)(A + (size_t)(m0 + r) * 64 + kbase + c4);
            uint32_t* da = &As[r * 36 + c4];
            da[0] = f2tf32(va.x); da[1] = f2tf32(va.y); da[2] = f2tf32(va.z); da[3] = f2tf32(va.w);
        }
#pragma unroll
        for (int i = t; i < 512; i += 256) {
            int r = i >> 3, c4 = (i & 7) << 2;
            float4 vb = *(const float4*)(B + (size_t)(n0 + r) * 64 + kbase + c4);
            uint32_t* db = &Bs[r * 36 + c4];
            db[0] = f2tf32(vb.x); db[1] = f2tf32(vb.y); db[2] = f2tf32(vb.z); db[3] = f2tf32(vb.w);
        }
        __syncthreads();
#pragma unroll
        for (int k0 = 0; k0 < 32; k0 += 8) {
            uint32_t af[2][4];
#pragma unroll
            for (int mt = 0; mt < 2; mt++) {
                int row = wm + (mt << 4) + grp;
                af[mt][0] = As[row * 36 + k0 + tig];
                af[mt][1] = As[(row + 8) * 36 + k0 + tig];
                af[mt][2] = As[row * 36 + k0 + tig + 4];
                af[mt][3] = As[(row + 8) * 36 + k0 + tig + 4];
            }
#pragma unroll
            for (int nt = 0; nt < 4; nt++) {
                int col = wn + (nt << 3) + grp;
                uint32_t b0 = Bs[col * 36 + k0 + tig];
                uint32_t b1 = Bs[col * 36 + k0 + tig + 4];
#pragma unroll
                for (int mt = 0; mt < 2; mt++) {
                    asm volatile(
                        "mma.sync.aligned.m16n8k8.row.col.f32.tf32.tf32.f32 "
                        "{%0,%1,%2,%3}, {%4,%5,%6,%7}, {%8,%9}, {%0,%1,%2,%3};\n"
                        : "+f"(acc[mt][nt][0]), "+f"(acc[mt][nt][1]),
                          "+f"(acc[mt][nt][2]), "+f"(acc[mt][nt][3])
                        : "r"(af[mt][0]), "r"(af[mt][1]), "r"(af[mt][2]), "r"(af[mt][3]),
                          "r"(b0), "r"(b1));
                }
            }
        }
        __syncthreads();
    }
#pragma unroll
    for (int mt = 0; mt < 2; mt++) {
        int row = m0 + wm + (mt << 4) + grp;
#pragma unroll
        for (int nt = 0; nt < 4; nt++) {
            int col = n0 + wn + (nt << 3) + (tig << 1);
            float b0v = bias[col], b1v = bias[col + 1];
            *(float2*)(C + (size_t)row * 4096 + col) =
                make_float2(acc[mt][nt][0] + b0v, acc[mt][nt][1] + b1v);
            *(float2*)(C + (size_t)(row + 8) * 4096 + col) =
                make_float2(acc[mt][nt][2] + b0v, acc[mt][nt][3] + b1v);
        }
    }
}

// ---------------- generic K=64 GEMM (root conv epilogue; zeroes agg after read) -------
__global__ void k_gemm64(const float* __restrict__ A, const float* __restrict__ B,
                         const float* __restrict__ bias, float* __restrict__ C,
                         int Ncols, int epi, float* __restrict__ agg,
                         const float* __restrict__ deg) {
    __shared__ float As[64 * 65];
    __shared__ float Bs[64 * 65];
    int t = threadIdx.x;
    int m0 = blockIdx.y << 6, n0 = blockIdx.x << 6;
    int r = t >> 4, c4 = (t & 15) << 2;
#pragma unroll
    for (int rr = 0; rr < 64; rr += 16) {
        float4 va = *(const float4*)(A + (size_t)(m0 + r + rr) * 64 + c4);
        As[(r + rr) * 65 + c4 + 0] = va.x;
        As[(r + rr) * 65 + c4 + 1] = va.y;
        As[(r + rr) * 65 + c4 + 2] = va.z;
        As[(r + rr) * 65 + c4 + 3] = va.w;
        float4 vb = *(const float4*)(B + (size_t)(n0 + r + rr) * 64 + c4);
        Bs[(r + rr) * 65 + c4 + 0] = vb.x;
        Bs[(r + rr) * 65 + c4 + 1] = vb.y;
        Bs[(r + rr) * 65 + c4 + 2] = vb.z;
        Bs[(r + rr) * 65 + c4 + 3] = vb.w;
    }
    __syncthreads();
    int tn = (t & 15) << 2;
    int tm = (t >> 4) << 2;
    float acc[4][4] = {};
#pragma unroll 8
    for (int k = 0; k < 64; k++) {
        float a0 = As[(tm + 0) * 65 + k];
        float a1 = As[(tm + 1) * 65 + k];
        float a2 = As[(tm + 2) * 65 + k];
        float a3 = As[(tm + 3) * 65 + k];
        float b0 = Bs[(tn + 0) * 65 + k];
        float b1 = Bs[(tn + 1) * 65 + k];
        float b2 = Bs[(tn + 2) * 65 + k];
        float b3 = Bs[(tn + 3) * 65 + k];
        acc[0][0] += a0 * b0; acc[0][1] += a0 * b1; acc[0][2] += a0 * b2; acc[0][3] += a0 * b3;
        acc[1][0] += a1 * b0; acc[1][1] += a1 * b1; acc[1][2] += a1 * b2; acc[1][3] += a1 * b3;
        acc[2][0] += a2 * b0; acc[2][1] += a2 * b1; acc[2][2] += a2 * b2; acc[2][3] += a2 * b3;
        acc[3][0] += a3 * b0; acc[3][1] += a3 * b1; acc[3][2] += a3 * b2; acc[3][3] += a3 * b3;
    }
#pragma unroll
    for (int i = 0; i < 4; i++) {
        int gm = m0 + tm + i;
        float vals[4];
#pragma unroll
        for (int j = 0; j < 4; j++) {
            float v = acc[i][j] + bias[n0 + tn + j];
            if (epi == 1) {
                size_t ai = (size_t)gm * 64 + n0 + tn + j;
                v += agg[ai] * (1.0f / fmaxf(deg[gm], 1.0f));
                agg[ai] = 0.0f;   // reset for next iteration's atomics
                v = fmaxf(v, 0.0f);
            }
            vals[j] = v;
        }
        *(float4*)(C + (size_t)gm * Ncols + n0 + tn) =
            make_float4(vals[0], vals[1], vals[2], vals[3]);
    }
}

// ---------------- per-edge einsum + scatter (streaming loads) ----------------
__global__ void k_msg(const float* __restrict__ x, const int* __restrict__ eidx,
                      const float* __restrict__ ew, float* __restrict__ agg) {
    int w = threadIdx.x >> 5, lane = threadIdx.x & 31;
    int e = blockIdx.x * 8 + w;
    int src = eidx[e], dst = eidx[NE + e];
    __shared__ float so[8][64];
    so[w][lane] = x[(size_t)src * 64 + lane];
    so[w][lane + 32] = x[(size_t)src * 64 + 32 + lane];
    __syncwarp();
    int half = lane >> 4;       // 0: even rows, 1: odd rows
    int cq = lane & 15;         // column quad
    const float4* p = (const float4*)(ew + (size_t)e * 4096) + cq;
    float a0 = 0.0f, a1 = 0.0f, a2 = 0.0f, a3 = 0.0f;
#pragma unroll 16
    for (int j = 0; j < 32; j++) {
        int row = (j << 1) + half;
        float s = so[w][row];
        float4 v = __ldcs(p + (row << 4));   // evict-first: zero-reuse stream
        a0 += s * v.x; a1 += s * v.y; a2 += s * v.z; a3 += s * v.w;
    }
    a0 += __shfl_xor_sync(0xffffffffu, a0, 16);
    a1 += __shfl_xor_sync(0xffffffffu, a1, 16);
    a2 += __shfl_xor_sync(0xffffffffu, a2, 16);
    a3 += __shfl_xor_sync(0xffffffffu, a3, 16);
    if (half == 0) {
        float* dp = &agg[(size_t)dst * 64 + (cq << 2)];
        atomicAdd(dp + 0, a0);
        atomicAdd(dp + 1, a1);
        atomicAdd(dp + 2, a2);
        atomicAdd(dp + 3, a3);
    }
}

// ---------------- fused GRU ----------------
__global__ void __launch_bounds__(512, 1)
k_gru_fused(const float* __restrict__ m, const float* __restrict__ wihT,
            const float* __restrict__ whhT, const float* __restrict__ bih,
            const float* __restrict__ bhh, float* __restrict__ x) {
    __shared__ float sm[64][64];
    __shared__ float sx[64][64];
    int t = threadIdx.x;
    int n0 = blockIdx.x << 6;
    for (int i = t; i < 64 * 16; i += 512) {
        int r = i >> 4, c = (i & 15) << 2;
        *(float4*)&sm[r][c] = *(const float4*)(m + (size_t)(n0 + r) * 64 + c);
        *(float4*)&sx[r][c] = *(const float4*)(x + (size_t)(n0 + r) * 64 + c);
    }
    __syncthreads();
    int o = t & 63, grp = t >> 6;
    int nb = grp << 3;
    float a0[8] = {}, a1[8] = {}, a2[8] = {}, b0[8] = {}, b1[8] = {}, b2[8] = {};
#pragma unroll 4
    for (int k = 0; k < 64; k++) {
        float wi0 = wihT[k * 192 + o];
        float wi1 = wihT[k * 192 + 64 + o];
        float wi2 = wihT[k * 192 + 128 + o];
        float wh0 = whhT[k * 192 + o];
        float wh1 = whhT[k * 192 + 64 + o];
        float wh2 = whhT[k * 192 + 128 + o];
#pragma unroll
        for (int j = 0; j < 8; j++) {
            float mv = sm[nb + j][k];
            float xv = sx[nb + j][k];
            a0[j] += mv * wi0; a1[j] += mv * wi1; a2[j] += mv * wi2;
            b0[j] += xv * wh0; b1[j] += xv * wh1; b2[j] += xv * wh2;
        }
    }
    float bi0 = bih[o], bi1 = bih[64 + o], bi2 = bih[128 + o];
    float bh0 = bhh[o], bh1 = bhh[64 + o], bh2 = bhh[128 + o];
#pragma unroll
    for (int j = 0; j < 8; j++) {
        int n = n0 + nb + j;
        float r = sigf(a0[j] + bi0 + b0[j] + bh0);
        float z = sigf(a1[j] + bi1 + b1[j] + bh1);
        float nn = tanhf(a2[j] + bi2 + r * (b2[j] + bh2));
        float h = sx[nb + j][o];
        x[(size_t)n * 64 + o] = (1.0f - z) * nn + z * h;
    }
}

// ---------------- fused Set2Set (6 steps) + memory LSTM (R6-verified) ----------------
__global__ void __launch_bounds__(256) k_pool(
    const float* __restrict__ x,
    const float* __restrict__ s2swihT, const float* __restrict__ s2swhhT,
    const float* __restrict__ s2s_bih, const float* __restrict__ s2s_bhh,
    const float* __restrict__ memwihT, const float* __restrict__ mem_bih,
    const float* __restrict__ mem_bhh,
    float* __restrict__ hx, float* __restrict__ out, int out_size) {
    int g = blockIdx.x, t = threadIdx.x;
    __shared__ float so[64][65];
    __shared__ float q[128], hh[64], ch[64], sgate[256], sa[64], red[64];
    for (int idx = t; idx < 4096; idx += 256) {
        int n = idx >> 6, c = idx & 63;
        so[n][c] = x[((size_t)g * 64 + n) * 64 + c];
    }
    if (t < 128) q[t] = 0.0f;
    if (t < 64) { hh[t] = 0.0f; ch[t] = 0.0f; }
    __syncthreads();
    for (int step = 0; step < 6; step++) {
        float acc = s2s_bih[t] + s2s_bhh[t];
#pragma unroll 4
        for (int j = 0; j < 128; j++) acc += q[j] * s2swihT[j * 256 + t];
#pragma unroll 4
        for (int j = 0; j < 64; j++) acc += hh[j] * s2swhhT[j * 256 + t];
        sgate[t] = acc;
        __syncthreads();
        if (t < 64) {
            float c = sigf(sgate[64 + t]) * ch[t] + sigf(sgate[t]) * tanhf(sgate[128 + t]);
            float h = sigf(sgate[192 + t]) * tanhf(c);
            ch[t] = c; hh[t] = h;
        }
        __syncthreads();
        float e = 0.0f;
        if (t < 64) {
#pragma unroll 8
            for (int c = 0; c < 64; c++) e += so[t][c] * hh[c];
            red[t] = e;
        }
        __syncthreads();
        if (t < 64) {
            float mx = -1e30f;
#pragma unroll 8
            for (int n = 0; n < 64; n++) mx = fmaxf(mx, red[n]);
            sa[t] = expf(e - mx);
        }
        __syncthreads();
        if (t < 64) {
            float ssum = 0.0f, rr = 0.0f;
#pragma unroll 8
            for (int n = 0; n < 64; n++) { ssum += sa[n]; rr += sa[n] * so[n][t]; }
            q[t] = hh[t];
            q[64 + t] = rr / ssum;
        }
        __syncthreads();
    }
    float acc = mem_bih[t] + mem_bhh[t];
#pragma unroll 4
    for (int j = 0; j < 128; j++) acc += q[j] * memwihT[j * 256 + t];
    sgate[t] = acc;
    __syncthreads();
    if (t < 64) {
        float c = sigf(sgate[t]) * tanhf(sgate[128 + t]);
        float h = sigf(sgate[192 + t]) * tanhf(c);
        hx[g * 64 + t] = h;
        int base = NT * 6;
        if (out_size >= base + 2 * NG * D) {
            out[base + g * 64 + t] = h;
            out[base + NG * 64 + g * 64 + t] = c;
        }
    }
}

// ---------------- final gather + MLP: 8 torsions per block (R6-verified) -------------
__global__ void __launch_bounds__(256) k_final8(
    const float* __restrict__ x, const float* __restrict__ hx,
    const int* __restrict__ nonring, const float* __restrict__ lin1T,
    const float* __restrict__ lin1b, const float* __restrict__ lin2w,
    const float* __restrict__ lin2b, float* __restrict__ out) {
    int t = threadIdx.x;
    int r0 = blockIdx.x << 3;
    __shared__ float feat[8][320];
    __shared__ float o1[8][64];
    for (int idx = t; idx < 8 * 320; idx += 256) {
        int rr = idx / 320, f = idx % 320;
        int linear = (r0 + rr) * 320 + f;
        int c = linear / (NT * 5);
        int rem = linear % (NT * 5);
        int tt = rem / 5;
        int s = rem % 5;
        float v;
        if (s == 0)
            v = hx[(tt / TPQ) * 64 + c];
        else
            v = x[(size_t)nonring[(s - 1) * NT + tt] * 64 + c];
        feat[rr][f] = v;
    }
    __syncthreads();
    int o = t & 63, tr = t >> 6;
#pragma unroll
    for (int pass = 0; pass < 2; pass++) {
        int rr = tr + (pass << 2);
        float acc = lin1b[o];
#pragma unroll 8
        for (int f = 0; f < 320; f++) acc += feat[rr][f] * lin1T[f * 64 + o];
        o1[rr][o] = fmaxf(acc, 0.0f);
    }
    __syncthreads();
    if (t < 48) {
        int rr = t / 6, a = t % 6;
        float s = lin2b[a];
#pragma unroll 8
        for (int j = 0; j < 64; j++) s += o1[rr][j] * lin2w[a * 64 + j];
        out[(r0 + rr) * 6 + a] = s;
    }
}

// ---------------- host side (launches ONLY) ----------------
extern "C" void kernel_launch(void* const* d_in, const int* in_sizes, int n_in,
                              void* d_out, int out_size) {
    const float* x_in = (const float*)d_in[0];
    const float* edge_attr = (const float*)d_in[1];
    const int* edge_index = (const int*)d_in[2];
    const int* nonring = (const int*)d_in[4];
    int wb = (n_in >= 32) ? 8 : 6;
    const float* lin0_w = (const float*)d_in[wb + 0];
    const float* lin0_b = (const float*)d_in[wb + 1];
    const float* e1_w = (const float*)d_in[wb + 2];
    const float* e1_b = (const float*)d_in[wb + 3];
    const float* e2_w = (const float*)d_in[wb + 4];
    const float* e2_b = (const float*)d_in[wb + 5];
    const float* root_w = (const float*)d_in[wb + 6];
    const float* conv_b = (const float*)d_in[wb + 7];
    const float* gru_wih = (const float*)d_in[wb + 8];
    const float* gru_whh = (const float*)d_in[wb + 9];
    const float* gru_bih = (const float*)d_in[wb + 10];
    const float* gru_bhh = (const float*)d_in[wb + 11];
    const float* s2s_wih = (const float*)d_in[wb + 12];
    const float* s2s_whh = (const float*)d_in[wb + 13];
    const float* s2s_bih = (const float*)d_in[wb + 14];
    const float* s2s_bhh = (const float*)d_in[wb + 15];
    const float* mem_wih = (const float*)d_in[wb + 16];
    const float* mem_bih = (const float*)d_in[wb + 18];
    const float* mem_bhh = (const float*)d_in[wb + 19];
    const float* lin1_w = (const float*)d_in[wb + 20];
    const float* lin1_b = (const float*)d_in[wb + 21];
    const float* lin2_w = (const float*)d_in[wb + 22];
    const float* lin2_b = (const float*)d_in[wb + 23];
    float* out = (float*)d_out;

    float *ew, *hidden, *xb, *agg, *m, *deg, *rootT, *gruWihT, *gruWhhT;
    float *s2swihT, *s2swhhT, *memwihT, *lin1T, *hx;
    cudaGetSymbolAddress((void**)&ew, g_ew);
    cudaGetSymbolAddress((void**)&hidden, g_hidden);
    cudaGetSymbolAddress((void**)&xb, g_x);
    cudaGetSymbolAddress((void**)&agg, g_agg);
    cudaGetSymbolAddress((void**)&m, g_m);
    cudaGetSymbolAddress((void**)&deg, g_deg);
    cudaGetSymbolAddress((void**)&rootT, g_rootT);
    cudaGetSymbolAddress((void**)&gruWihT, g_gru_wihT);
    cudaGetSymbolAddress((void**)&gruWhhT, g_gru_whhT);
    cudaGetSymbolAddress((void**)&s2swihT, g_s2s_wihT);
    cudaGetSymbolAddress((void**)&s2swhhT, g_s2s_whhT);
    cudaGetSymbolAddress((void**)&memwihT, g_mem_wihT);
    cudaGetSymbolAddress((void**)&lin1T, g_lin1T);
    cudaGetSymbolAddress((void**)&hx, g_hx);

    // 1: edge hidden
    k_hidden<<<(NE * D + 255) / 256, 256>>>(edge_attr, e1_w, e1_b, hidden);
    // 2: node projection + zero agg/deg
    k_lin0z<<<(NNODES * D + 255) / 256, 256>>>(x_in, lin0_w, lin0_b, xb, agg, deg);
    // 3: ew GEMM
    k_ew_tf32<<<dim3(4096 / 64, NE / 128), 256>>>(hidden, e2_w, e2_b, ew);
    // 4: msg iteration 0 — profiled slot (only needs launches 1-3)
    k_msg<<<NE / 8, 256>>>(xb, edge_index, ew, agg);
    // 5: degree histogram (needed by gemm64, launched before it)
    k_deg<<<(NE + 255) / 256, 256>>>(edge_index, deg);
    // 6-7: weight transposes
    k_transpose<<<(64 * 64 + 255) / 256, 256>>>(root_w, rootT, 64, 64);
    k_prep<<<(126976 + 255) / 256, 256>>>(gru_wih, gru_whh, s2s_wih, s2s_whh, mem_wih,
                                          lin1_w, gruWihT, gruWhhT, s2swihT, s2swhhT,
                                          memwihT, lin1T);

    // iteration 0 tail, then iterations 1..5 (gemm64 epi zeroes agg for next msg)
    k_gemm64<<<dim3(1, NNODES / 64), 256>>>(xb, rootT, conv_b, m, 64, 1, agg, deg);
    k_gru_fused<<<256, 512>>>(m, gruWihT, gruWhhT, gru_bih, gru_bhh, xb);
    for (int it = 1; it < 6; it++) {
        k_msg<<<NE / 8, 256>>>(xb, edge_index, ew, agg);
        k_gemm64<<<dim3(1, NNODES / 64), 256>>>(xb, rootT, conv_b, m, 64, 1, agg, deg);
        k_gru_fused<<<256, 512>>>(m, gruWihT, gruWhhT, gru_bih, gru_bhh, xb);
    }

    // fused Set2Set + memory LSTM, then final gather + MLP
    k_pool<<<NG, 256>>>(xb, s2swihT, s2swhhT, s2s_bih, s2s_bhh, memwihT, mem_bih,
                        mem_bhh, hx, out, out_size);
    k_final8<<<NT / 8, 256>>>(xb, hx, nonring, lin1T, lin1_b, lin2_w, lin2_b, out);
}

// round 15
// speedup vs baseline: 1.4815x; 1.0328x over previous
#include <cuda_runtime.h>
#include <cuda_fp16.h>
#include <cstdint>
#include <cstdio>

#define D 64
#define NNODES 16384
#define NE 32768
#define NG 256
#define TPQ 12
#define NT (NG * TPQ)   // 3072

// ---------------- scratch (static device allocations) ----------------
__device__ __half g_ew[(size_t)NE * (D * D)];  // 256 MB (fp16)
__device__ float g_hidden[NE * D];
__device__ float g_x[NNODES * D];              // out == h
__device__ float g_agg[NNODES * D];
__device__ float g_m[NNODES * D];
__device__ float g_deg[NNODES];
__device__ float g_rootT[D * D];
__device__ float g_gru_wihT[64 * 192];
__device__ float g_gru_whhT[64 * 192];
__device__ float g_s2s_wihT[128 * 256];
__device__ float g_s2s_whhT[64 * 256];
__device__ float g_mem_wihT[128 * 256];
__device__ float g_lin1T[320 * 64];
__device__ float g_hx[NG * D];

__device__ __forceinline__ float sigf(float x) { return 1.0f / (1.0f + expf(-x)); }
__device__ __forceinline__ uint32_t f2tf32(float f) {
    uint32_t r; asm("cvt.rna.tf32.f32 %0, %1;" : "=r"(r) : "f"(f)); return r;
}

// ---------------- prologue kernels ----------------
__global__ void k_hidden(const float* __restrict__ ea, const float* __restrict__ w,
                         const float* __restrict__ b, float* __restrict__ out) {
    int i = blockIdx.x * blockDim.x + threadIdx.x;
    if (i >= NE * D) return;
    int e = i >> 6, j = i & 63;
    float v = b[j];
#pragma unroll
    for (int k = 0; k < 6; k++) v += ea[e * 6 + k] * w[j * 6 + k];
    out[i] = fmaxf(v, 0.0f);
}

__global__ void k_lin0z(const float* __restrict__ x, const float* __restrict__ w,
                        const float* __restrict__ b, float* __restrict__ out,
                        float* __restrict__ agg, float* __restrict__ deg) {
    int i = blockIdx.x * blockDim.x + threadIdx.x;
    if (i >= NNODES * D) return;
    int n = i >> 6, o = i & 63;
    float v = b[o] + x[n * 3 + 0] * w[o * 3 + 0] + x[n * 3 + 1] * w[o * 3 + 1] +
              x[n * 3 + 2] * w[o * 3 + 2];
    out[i] = fmaxf(v, 0.0f);
    agg[i] = 0.0f;
    if (o == 0) deg[n] = 0.0f;
}

__global__ void k_transpose(const float* __restrict__ in, float* __restrict__ out, int R, int C) {
    int i = blockIdx.x * blockDim.x + threadIdx.x;
    if (i < R * C) {
        int r = i / C, c = i % C;
        out[c * R + r] = in[i];
    }
}

__global__ void k_prep(const float* __restrict__ gru_wih, const float* __restrict__ gru_whh,
                       const float* __restrict__ s2s_wih, const float* __restrict__ s2s_whh,
                       const float* __restrict__ mem_wih, const float* __restrict__ lin1_w,
                       float* __restrict__ gruWihT, float* __restrict__ gruWhhT,
                       float* __restrict__ s2swihT, float* __restrict__ s2swhhT,
                       float* __restrict__ memwihT, float* __restrict__ lin1T) {
    int i = blockIdx.x * blockDim.x + threadIdx.x;
    if (i < 12288) {
        int r = i / 64, c = i % 64;
        gruWihT[c * 192 + r] = gru_wih[i];
    } else if (i < 24576) {
        int j = i - 12288;
        int r = j / 64, c = j % 64;
        gruWhhT[c * 192 + r] = gru_whh[j];
    } else if (i < 57344) {
        int j = i - 24576;
        int r = j / 128, c = j % 128;
        s2swihT[c * 256 + r] = s2s_wih[j];
    } else if (i < 73728) {
        int j = i - 57344;
        int r = j / 64, c = j % 64;
        s2swhhT[c * 256 + r] = s2s_whh[j];
    } else if (i < 106496) {
        int j = i - 73728;
        int r = j / 128, c = j % 128;
        memwihT[c * 256 + r] = mem_wih[j];
    } else if (i < 126976) {
        int j = i - 106496;
        int r = j / 320, c = j % 320;
        lin1T[c * 64 + r] = lin1_w[j];
    }
}

__global__ void k_deg(const int* __restrict__ eidx, float* __restrict__ deg) {
    int e = blockIdx.x * blockDim.x + threadIdx.x;
    if (e < NE) atomicAdd(&deg[eidx[NE + e]], 1.0f);
}

// ---------------- 3xTF32 MMA GEMM -> fp16: ew = hidden @ e2_w^T + b2 ------------------
// 128x64 block tile, K staged 16 at a time, hi/lo operand split (error ~2^-22).
// smem: (128+64)*20*2 words = 30 KB. 8 warps (4m x 2n), warp tile 32x32.
__global__ void __launch_bounds__(256, 2) k_ew_tf32(
    const float* __restrict__ A, const float* __restrict__ B,
    const float* __restrict__ bias, __half* __restrict__ C) {
    __shared__ uint32_t AsH[128 * 20];
    __shared__ uint32_t AsL[128 * 20];
    __shared__ uint32_t BsH[64 * 20];
    __shared__ uint32_t BsL[64 * 20];
    int t = threadIdx.x;
    int m0 = blockIdx.y << 7, n0 = blockIdx.x << 6;
    int lane = t & 31, w = t >> 5;
    int wm = (w >> 1) << 5;
    int wn = (w & 1) << 5;
    int grp = lane >> 2, tig = lane & 3;
    float acc[2][4][4];
#pragma unroll
    for (int a = 0; a < 2; a++)
#pragma unroll
        for (int b = 0; b < 4; b++)
#pragma unroll
            for (int c = 0; c < 4; c++) acc[a][b][c] = 0.0f;

#pragma unroll
    for (int ks = 0; ks < 4; ks++) {
        int kbase = ks << 4;
        // stage A: 128 rows x 16 cols (2 float4/thread)
#pragma unroll
        for (int i = t; i < 512; i += 256) {
            int r = i >> 2, c4 = (i & 3) << 2;
            float4 va = *(const float4*)(A + (size_t)(m0 + r) * 64 + kbase + c4);
            uint32_t* dh = &AsH[r * 20 + c4];
            uint32_t* dl = &AsL[r * 20 + c4];
            uint32_t h0 = f2tf32(va.x), h1 = f2tf32(va.y), h2 = f2tf32(va.z), h3 = f2tf32(va.w);
            dh[0] = h0; dh[1] = h1; dh[2] = h2; dh[3] = h3;
            dl[0] = f2tf32(va.x - __uint_as_float(h0));
            dl[1] = f2tf32(va.y - __uint_as_float(h1));
            dl[2] = f2tf32(va.z - __uint_as_float(h2));
            dl[3] = f2tf32(va.w - __uint_as_float(h3));
        }
        // stage B: 64 rows x 16 cols (1 float4/thread)
        {
            int r = t >> 2, c4 = (t & 3) << 2;
            float4 vb = *(const float4*)(B + (size_t)(n0 + r) * 64 + kbase + c4);
            uint32_t* dh = &BsH[r * 20 + c4];
            uint32_t* dl = &BsL[r * 20 + c4];
            uint32_t h0 = f2tf32(vb.x), h1 = f2tf32(vb.y), h2 = f2tf32(vb.z), h3 = f2tf32(vb.w);
            dh[0] = h0; dh[1] = h1; dh[2] = h2; dh[3] = h3;
            dl[0] = f2tf32(vb.x - __uint_as_float(h0));
            dl[1] = f2tf32(vb.y - __uint_as_float(h1));
            dl[2] = f2tf32(vb.z - __uint_as_float(h2));
            dl[3] = f2tf32(vb.w - __uint_as_float(h3));
        }
        __syncthreads();
#pragma unroll
        for (int k0 = 0; k0 < 16; k0 += 8) {
            uint32_t afh[2][4], afl[2][4];
#pragma unroll
            for (int mt = 0; mt < 2; mt++) {
                int row = wm + (mt << 4) + grp;
                int i0 = row * 20 + k0 + tig;
                int i1 = (row + 8) * 20 + k0 + tig;
                afh[mt][0] = AsH[i0];     afh[mt][1] = AsH[i1];
                afh[mt][2] = AsH[i0 + 4]; afh[mt][3] = AsH[i1 + 4];
                afl[mt][0] = AsL[i0];     afl[mt][1] = AsL[i1];
                afl[mt][2] = AsL[i0 + 4]; afl[mt][3] = AsL[i1 + 4];
            }
#pragma unroll
            for (int nt = 0; nt < 4; nt++) {
                int col = wn + (nt << 3) + grp;
                int j0 = col * 20 + k0 + tig;
                uint32_t bh0 = BsH[j0], bh1 = BsH[j0 + 4];
                uint32_t bl0 = BsL[j0], bl1 = BsL[j0 + 4];
#pragma unroll
                for (int mt = 0; mt < 2; mt++) {
                    // hi * lo
                    asm volatile(
                        "mma.sync.aligned.m16n8k8.row.col.f32.tf32.tf32.f32 "
                        "{%0,%1,%2,%3}, {%4,%5,%6,%7}, {%8,%9}, {%0,%1,%2,%3};\n"
                        : "+f"(acc[mt][nt][0]), "+f"(acc[mt][nt][1]),
                          "+f"(acc[mt][nt][2]), "+f"(acc[mt][nt][3])
                        : "r"(afh[mt][0]), "r"(afh[mt][1]), "r"(afh[mt][2]), "r"(afh[mt][3]),
                          "r"(bl0), "r"(bl1));
                    // lo * hi
                    asm volatile(
                        "mma.sync.aligned.m16n8k8.row.col.f32.tf32.tf32.f32 "
                        "{%0,%1,%2,%3}, {%4,%5,%6,%7}, {%8,%9}, {%0,%1,%2,%3};\n"
                        : "+f"(acc[mt][nt][0]), "+f"(acc[mt][nt][1]),
                          "+f"(acc[mt][nt][2]), "+f"(acc[mt][nt][3])
                        : "r"(afl[mt][0]), "r"(afl[mt][1]), "r"(afl[mt][2]), "r"(afl[mt][3]),
                          "r"(bh0), "r"(bh1));
                    // hi * hi
                    asm volatile(
                        "mma.sync.aligned.m16n8k8.row.col.f32.tf32.tf32.f32 "
                        "{%0,%1,%2,%3}, {%4,%5,%6,%7}, {%8,%9}, {%0,%1,%2,%3};\n"
                        : "+f"(acc[mt][nt][0]), "+f"(acc[mt][nt][1]),
                          "+f"(acc[mt][nt][2]), "+f"(acc[mt][nt][3])
                        : "r"(afh[mt][0]), "r"(afh[mt][1]), "r"(afh[mt][2]), "r"(afh[mt][3]),
                          "r"(bh0), "r"(bh1));
                }
            }
        }
        __syncthreads();
    }
#pragma unroll
    for (int mt = 0; mt < 2; mt++) {
        int row = m0 + wm + (mt << 4) + grp;
#pragma unroll
        for (int nt = 0; nt < 4; nt++) {
            int col = n0 + wn + (nt << 3) + (tig << 1);
            float b0v = bias[col], b1v = bias[col + 1];
            *(__half2*)(C + (size_t)row * 4096 + col) =
                __floats2half2_rn(acc[mt][nt][0] + b0v, acc[mt][nt][1] + b1v);
            *(__half2*)(C + (size_t)(row + 8) * 4096 + col) =
                __floats2half2_rn(acc[mt][nt][2] + b0v, acc[mt][nt][3] + b1v);
        }
    }
}

// ---------------- generic K=64 GEMM (root conv epilogue; zeroes agg after read) -------
__global__ void k_gemm64(const float* __restrict__ A, const float* __restrict__ B,
                         const float* __restrict__ bias, float* __restrict__ C,
                         int Ncols, int epi, float* __restrict__ agg,
                         const float* __restrict__ deg) {
    __shared__ float As[64 * 65];
    __shared__ float Bs[64 * 65];
    int t = threadIdx.x;
    int m0 = blockIdx.y << 6, n0 = blockIdx.x << 6;
    int r = t >> 4, c4 = (t & 15) << 2;
#pragma unroll
    for (int rr = 0; rr < 64; rr += 16) {
        float4 va = *(const float4*)(A + (size_t)(m0 + r + rr) * 64 + c4);
        As[(r + rr) * 65 + c4 + 0] = va.x;
        As[(r + rr) * 65 + c4 + 1] = va.y;
        As[(r + rr) * 65 + c4 + 2] = va.z;
        As[(r + rr) * 65 + c4 + 3] = va.w;
        float4 vb = *(const float4*)(B + (size_t)(n0 + r + rr) * 64 + c4);
        Bs[(r + rr) * 65 + c4 + 0] = vb.x;
        Bs[(r + rr) * 65 + c4 + 1] = vb.y;
        Bs[(r + rr) * 65 + c4 + 2] = vb.z;
        Bs[(r + rr) * 65 + c4 + 3] = vb.w;
    }
    __syncthreads();
    int tn = (t & 15) << 2;
    int tm = (t >> 4) << 2;
    float acc[4][4] = {};
#pragma unroll 8
    for (int k = 0; k < 64; k++) {
        float a0 = As[(tm + 0) * 65 + k];
        float a1 = As[(tm + 1) * 65 + k];
        float a2 = As[(tm + 2) * 65 + k];
        float a3 = As[(tm + 3) * 65 + k];
        float b0 = Bs[(tn + 0) * 65 + k];
        float b1 = Bs[(tn + 1) * 65 + k];
        float b2 = Bs[(tn + 2) * 65 + k];
        float b3 = Bs[(tn + 3) * 65 + k];
        acc[0][0] += a0 * b0; acc[0][1] += a0 * b1; acc[0][2] += a0 * b2; acc[0][3] += a0 * b3;
        acc[1][0] += a1 * b0; acc[1][1] += a1 * b1; acc[1][2] += a1 * b2; acc[1][3] += a1 * b3;
        acc[2][0] += a2 * b0; acc[2][1] += a2 * b1; acc[2][2] += a2 * b2; acc[2][3] += a2 * b3;
        acc[3][0] += a3 * b0; acc[3][1] += a3 * b1; acc[3][2] += a3 * b2; acc[3][3] += a3 * b3;
    }
#pragma unroll
    for (int i = 0; i < 4; i++) {
        int gm = m0 + tm + i;
        float vals[4];
#pragma unroll
        for (int j = 0; j < 4; j++) {
            float v = acc[i][j] + bias[n0 + tn + j];
            if (epi == 1) {
                size_t ai = (size_t)gm * 64 + n0 + tn + j;
                v += agg[ai] * (1.0f / fmaxf(deg[gm], 1.0f));
                agg[ai] = 0.0f;
                v = fmaxf(v, 0.0f);
            }
            vals[j] = v;
        }
        *(float4*)(C + (size_t)gm * Ncols + n0 + tn) =
            make_float4(vals[0], vals[1], vals[2], vals[3]);
    }
}

// ---------------- per-edge einsum + scatter (fp16 ew, streaming loads) ----------------
__global__ void k_msg(const float* __restrict__ x, const int* __restrict__ eidx,
                      const __half* __restrict__ ew, float* __restrict__ agg) {
    int w = threadIdx.x >> 5, lane = threadIdx.x & 31;
    int e = blockIdx.x * 8 + w;
    int src = eidx[e], dst = eidx[NE + e];
    __shared__ float so[8][64];
    so[w][lane] = x[(size_t)src * 64 + lane];
    so[w][lane + 32] = x[(size_t)src * 64 + 32 + lane];
    __syncwarp();
    int half_ = lane >> 4;      // 0: even rows, 1: odd rows
    int cq = lane & 15;         // column quad: cols [4cq, 4cq+4)
    const __half* base = ew + (size_t)e * 4096 + (cq << 2);
    float a0 = 0.0f, a1 = 0.0f, a2 = 0.0f, a3 = 0.0f;
#pragma unroll 16
    for (int j = 0; j < 32; j++) {
        int row = (j << 1) + half_;
        float s = so[w][row];
        uint2 raw = __ldcs((const uint2*)(base + (row << 6)));
        float2 f01 = __half22float2(*reinterpret_cast<__half2*>(&raw.x));
        float2 f23 = __half22float2(*reinterpret_cast<__half2*>(&raw.y));
        a0 += s * f01.x; a1 += s * f01.y; a2 += s * f23.x; a3 += s * f23.y;
    }
    a0 += __shfl_xor_sync(0xffffffffu, a0, 16);
    a1 += __shfl_xor_sync(0xffffffffu, a1, 16);
    a2 += __shfl_xor_sync(0xffffffffu, a2, 16);
    a3 += __shfl_xor_sync(0xffffffffu, a3, 16);
    if (half_ == 0) {
        float* dp = &agg[(size_t)dst * 64 + (cq << 2)];
        atomicAdd(dp + 0, a0);
        atomicAdd(dp + 1, a1);
        atomicAdd(dp + 2, a2);
        atomicAdd(dp + 3, a3);
    }
}

// ---------------- fused GRU ----------------
__global__ void __launch_bounds__(512, 1)
k_gru_fused(const float* __restrict__ m, const float* __restrict__ wihT,
            const float* __restrict__ whhT, const float* __restrict__ bih,
            const float* __restrict__ bhh, float* __restrict__ x) {
    __shared__ float sm[64][64];
    __shared__ float sx[64][64];
    int t = threadIdx.x;
    int n0 = blockIdx.x << 6;
    for (int i = t; i < 64 * 16; i += 512) {
        int r = i >> 4, c = (i & 15) << 2;
        *(float4*)&sm[r][c] = *(const float4*)(m + (size_t)(n0 + r) * 64 + c);
        *(float4*)&sx[r][c] = *(const float4*)(x + (size_t)(n0 + r) * 64 + c);
    }
    __syncthreads();
    int o = t & 63, grp = t >> 6;
    int nb = grp << 3;
    float a0[8] = {}, a1[8] = {}, a2[8] = {}, b0[8] = {}, b1[8] = {}, b2[8] = {};
#pragma unroll 4
    for (int k = 0; k < 64; k++) {
        float wi0 = wihT[k * 192 + o];
        float wi1 = wihT[k * 192 + 64 + o];
        float wi2 = wihT[k * 192 + 128 + o];
        float wh0 = whhT[k * 192 + o];
        float wh1 = whhT[k * 192 + 64 + o];
        float wh2 = whhT[k * 192 + 128 + o];
#pragma unroll
        for (int j = 0; j < 8; j++) {
            float mv = sm[nb + j][k];
            float xv = sx[nb + j][k];
            a0[j] += mv * wi0; a1[j] += mv * wi1; a2[j] += mv * wi2;
            b0[j] += xv * wh0; b1[j] += xv * wh1; b2[j] += xv * wh2;
        }
    }
    float bi0 = bih[o], bi1 = bih[64 + o], bi2 = bih[128 + o];
    float bh0 = bhh[o], bh1 = bhh[64 + o], bh2 = bhh[128 + o];
#pragma unroll
    for (int j = 0; j < 8; j++) {
        int n = n0 + nb + j;
        float r = sigf(a0[j] + bi0 + b0[j] + bh0);
        float z = sigf(a1[j] + bi1 + b1[j] + bh1);
        float nn = tanhf(a2[j] + bi2 + r * (b2[j] + bh2));
        float h = sx[nb + j][o];
        x[(size_t)n * 64 + o] = (1.0f - z) * nn + z * h;
    }
}

// ---------------- fused Set2Set (6 steps) + memory LSTM ----------------
__global__ void __launch_bounds__(256) k_pool(
    const float* __restrict__ x,
    const float* __restrict__ s2swihT, const float* __restrict__ s2swhhT,
    const float* __restrict__ s2s_bih, const float* __restrict__ s2s_bhh,
    const float* __restrict__ memwihT, const float* __restrict__ mem_bih,
    const float* __restrict__ mem_bhh,
    float* __restrict__ hx, float* __restrict__ out, int out_size) {
    int g = blockIdx.x, t = threadIdx.x;
    __shared__ float so[64][65];
    __shared__ float q[128], hh[64], ch[64], sgate[256], sa[64], red[64];
    for (int idx = t; idx < 4096; idx += 256) {
        int n = idx >> 6, c = idx & 63;
        so[n][c] = x[((size_t)g * 64 + n) * 64 + c];
    }
    if (t < 128) q[t] = 0.0f;
    if (t < 64) { hh[t] = 0.0f; ch[t] = 0.0f; }
    __syncthreads();
    for (int step = 0; step < 6; step++) {
        float acc = s2s_bih[t] + s2s_bhh[t];
#pragma unroll 4
        for (int j = 0; j < 128; j++) acc += q[j] * s2swihT[j * 256 + t];
#pragma unroll 4
        for (int j = 0; j < 64; j++) acc += hh[j] * s2swhhT[j * 256 + t];
        sgate[t] = acc;
        __syncthreads();
        if (t < 64) {
            float c = sigf(sgate[64 + t]) * ch[t] + sigf(sgate[t]) * tanhf(sgate[128 + t]);
            float h = sigf(sgate[192 + t]) * tanhf(c);
            ch[t] = c; hh[t] = h;
        }
        __syncthreads();
        float e = 0.0f;
        if (t < 64) {
#pragma unroll 8
            for (int c = 0; c < 64; c++) e += so[t][c] * hh[c];
            red[t] = e;
        }
        __syncthreads();
        if (t < 64) {
            float mx = -1e30f;
#pragma unroll 8
            for (int n = 0; n < 64; n++) mx = fmaxf(mx, red[n]);
            sa[t] = expf(e - mx);
        }
        __syncthreads();
        if (t < 64) {
            float ssum = 0.0f, rr = 0.0f;
#pragma unroll 8
            for (int n = 0; n < 64; n++) { ssum += sa[n]; rr += sa[n] * so[n][t]; }
            q[t] = hh[t];
            q[64 + t] = rr / ssum;
        }
        __syncthreads();
    }
    float acc = mem_bih[t] + mem_bhh[t];
#pragma unroll 4
    for (int j = 0; j < 128; j++) acc += q[j] * memwihT[j * 256 + t];
    sgate[t] = acc;
    __syncthreads();
    if (t < 64) {
        float c = sigf(sgate[t]) * tanhf(sgate[128 + t]);
        float h = sigf(sgate[192 + t]) * tanhf(c);
        hx[g * 64 + t] = h;
        int base = NT * 6;
        if (out_size >= base + 2 * NG * D) {
            out[base + g * 64 + t] = h;
            out[base + NG * 64 + g * 64 + t] = c;
        }
    }
}

// ---------------- final gather + MLP: 8 torsions per block ----------------
__global__ void __launch_bounds__(256) k_final8(
    const float* __restrict__ x, const float* __restrict__ hx,
    const int* __restrict__ nonring, const float* __restrict__ lin1T,
    const float* __restrict__ lin1b, const float* __restrict__ lin2w,
    const float* __restrict__ lin2b, float* __restrict__ out) {
    int t = threadIdx.x;
    int r0 = blockIdx.x << 3;
    __shared__ float feat[8][320];
    __shared__ float o1[8][64];
    for (int idx = t; idx < 8 * 320; idx += 256) {
        int rr = idx / 320, f = idx % 320;
        int linear = (r0 + rr) * 320 + f;
        int c = linear / (NT * 5);
        int rem = linear % (NT * 5);
        int tt = rem / 5;
        int s = rem % 5;
        float v;
        if (s == 0)
            v = hx[(tt / TPQ) * 64 + c];
        else
            v = x[(size_t)nonring[(s - 1) * NT + tt] * 64 + c];
        feat[rr][f] = v;
    }
    __syncthreads();
    int o = t & 63, tr = t >> 6;
#pragma unroll
    for (int pass = 0; pass < 2; pass++) {
        int rr = tr + (pass << 2);
        float acc = lin1b[o];
#pragma unroll 8
        for (int f = 0; f < 320; f++) acc += feat[rr][f] * lin1T[f * 64 + o];
        o1[rr][o] = fmaxf(acc, 0.0f);
    }
    __syncthreads();
    if (t < 48) {
        int rr = t / 6, a = t % 6;
        float s = lin2b[a];
#pragma unroll 8
        for (int j = 0; j < 64; j++) s += o1[rr][j] * lin2w[a * 64 + j];
        out[(r0 + rr) * 6 + a] = s;
    }
}

// ---------------- host side (launches ONLY) ----------------
extern "C" void kernel_launch(void* const* d_in, const int* in_sizes, int n_in,
                              void* d_out, int out_size) {
    const float* x_in = (const float*)d_in[0];
    const float* edge_attr = (const float*)d_in[1];
    const int* edge_index = (const int*)d_in[2];
    const int* nonring = (const int*)d_in[4];
    int wb = (n_in >= 32) ? 8 : 6;
    const float* lin0_w = (const float*)d_in[wb + 0];
    const float* lin0_b = (const float*)d_in[wb + 1];
    const float* e1_w = (const float*)d_in[wb + 2];
    const float* e1_b = (const float*)d_in[wb + 3];
    const float* e2_w = (const float*)d_in[wb + 4];
    const float* e2_b = (const float*)d_in[wb + 5];
    const float* root_w = (const float*)d_in[wb + 6];
    const float* conv_b = (const float*)d_in[wb + 7];
    const float* gru_wih = (const float*)d_in[wb + 8];
    const float* gru_whh = (const float*)d_in[wb + 9];
    const float* gru_bih = (const float*)d_in[wb + 10];
    const float* gru_bhh = (const float*)d_in[wb + 11];
    const float* s2s_wih = (const float*)d_in[wb + 12];
    const float* s2s_whh = (const float*)d_in[wb + 13];
    const float* s2s_bih = (const float*)d_in[wb + 14];
    const float* s2s_bhh = (const float*)d_in[wb + 15];
    const float* mem_wih = (const float*)d_in[wb + 16];
    const float* mem_bih = (const float*)d_in[wb + 18];
    const float* mem_bhh = (const float*)d_in[wb + 19];
    const float* lin1_w = (const float*)d_in[wb + 20];
    const float* lin1_b = (const float*)d_in[wb + 21];
    const float* lin2_w = (const float*)d_in[wb + 22];
    const float* lin2_b = (const float*)d_in[wb + 23];
    float* out = (float*)d_out;

    __half* ew;
    float *hidden, *xb, *agg, *m, *deg, *rootT, *gruWihT, *gruWhhT;
    float *s2swihT, *s2swhhT, *memwihT, *lin1T, *hx;
    cudaGetSymbolAddress((void**)&ew, g_ew);
    cudaGetSymbolAddress((void**)&hidden, g_hidden);
    cudaGetSymbolAddress((void**)&xb, g_x);
    cudaGetSymbolAddress((void**)&agg, g_agg);
    cudaGetSymbolAddress((void**)&m, g_m);
    cudaGetSymbolAddress((void**)&deg, g_deg);
    cudaGetSymbolAddress((void**)&rootT, g_rootT);
    cudaGetSymbolAddress((void**)&gruWihT, g_gru_wihT);
    cudaGetSymbolAddress((void**)&gruWhhT, g_gru_whhT);
    cudaGetSymbolAddress((void**)&s2swihT, g_s2s_wihT);
    cudaGetSymbolAddress((void**)&s2swhhT, g_s2s_whhT);
    cudaGetSymbolAddress((void**)&memwihT, g_mem_wihT);
    cudaGetSymbolAddress((void**)&lin1T, g_lin1T);
    cudaGetSymbolAddress((void**)&hx, g_hx);

    // 1: edge hidden
    k_hidden<<<(NE * D + 255) / 256, 256>>>(edge_attr, e1_w, e1_b, hidden);
    // 2: node projection + zero agg/deg
    k_lin0z<<<(NNODES * D + 255) / 256, 256>>>(x_in, lin0_w, lin0_b, xb, agg, deg);
    // 3: degree histogram
    k_deg<<<(NE + 255) / 256, 256>>>(edge_index, deg);
    // 4: ew GEMM (3xTF32 -> fp16) — profiled slot
    k_ew_tf32<<<dim3(4096 / 64, NE / 128), 256>>>(hidden, e2_w, e2_b, ew);
    // 5-6: weight transposes
    k_transpose<<<(64 * 64 + 255) / 256, 256>>>(root_w, rootT, 64, 64);
    k_prep<<<(126976 + 255) / 256, 256>>>(gru_wih, gru_whh, s2s_wih, s2s_whh, mem_wih,
                                          lin1_w, gruWihT, gruWhhT, s2swihT, s2swhhT,
                                          memwihT, lin1T);

    // 6 NNConv + GRU iterations (gemm64 epilogue zeroes agg for the next msg)
    for (int it = 0; it < 6; it++) {
        k_msg<<<NE / 8, 256>>>(xb, edge_index, ew, agg);
        k_gemm64<<<dim3(1, NNODES / 64), 256>>>(xb, rootT, conv_b, m, 64, 1, agg, deg);
        k_gru_fused<<<256, 512>>>(m, gruWihT, gruWhhT, gru_bih, gru_bhh, xb);
    }

    // fused Set2Set + memory LSTM, then final gather + MLP
    k_pool<<<NG, 256>>>(xb, s2swihT, s2swhhT, s2s_bih, s2s_bhh, memwihT, mem_bih,
                        mem_bhh, hx, out, out_size);
    k_final8<<<NT / 8, 256>>>(xb, hx, nonring, lin1T, lin1_b, lin2_w, lin2_b, out);
}